// round 13
// baseline (speedup 1.0000x reference)
#include <cuda_runtime.h>
#include <mma.h>
#include <math.h>

using namespace nvcuda;

#define BB 8
#define CC 256
#define NN 4096
#define MM 512
#define EE 16
#define NH 8
#define FFNH 2048
#define EPSV 1.1920929e-07f

// ------------- scratch (__device__ globals; no allocation allowed) ---------------
__device__ float g_PE  [NN * MM];             // pos_enc G@W2 (NO bias)
__device__ float g_RINV[BB * NN];             // patch rmsnorm rsqrt (written by k_scores_tc)
__device__ float g_Q   [128 * 512];           // q rows=(b,e) (includes bq)
__device__ float g_MOLN[128 * 512];           // normalized mol (residual)
__device__ float g_TQ  [BB * 128 * 256];      // tq' rows=(b, h*16+e), wp & 0.125 folded
__device__ float g_S   [(size_t)BB * 128 * NN];       // scores/probs  16.8 MB
__device__ float g_PAP [(size_t)16 * BB * 128 * 256]; // pa partials   16.8 MB
__device__ float g_OPEP[8 * 8 * 128 * 64];    // p@(pe+bv+b2) partials
__device__ float g_ATT0[128 * 512];           // attention out (pre-proj)
__device__ float g_ATT [128 * 512];           // attended (post residual)
__device__ float g_H1  [128 * 2048];          // ffn hidden

__device__ __forceinline__ float geluf(float x) {
    return 0.5f * x * (1.0f + erff(x * 0.70710678118654752440f));
}

template <int NWARPS, bool DOMAX>
__device__ __forceinline__ float blk_red(float v, float* red) {
    #pragma unroll
    for (int o = 16; o; o >>= 1) {
        float t = __shfl_xor_sync(0xffffffffu, v, o);
        v = DOMAX ? fmaxf(v, t) : v + t;
    }
    if ((threadIdx.x & 31) == 0) red[threadIdx.x >> 5] = v;
    __syncthreads();
    if (threadIdx.x < 32) {
        float r = (threadIdx.x < NWARPS) ? red[threadIdx.x] : (DOMAX ? -1e30f : 0.0f);
        #pragma unroll
        for (int o = NWARPS >> 1; o; o >>= 1) {
            float t = __shfl_xor_sync(0xffffffffu, r, o);
            r = DOMAX ? fmaxf(r, t) : r + t;
        }
        if (threadIdx.x == 0) red[0] = r;
    }
    __syncthreads();
    float s = red[0];
    __syncthreads();
    return s;
}

// ---------------- K1: PE = gelu(coords@W1+b1) @ W2 (tf32 TC, gelu fused) -----------
__global__ void __launch_bounds__(256) k_peg_tc(const float* __restrict__ w1,
                                                const float* __restrict__ b1,
                                                const float* __restrict__ w2) {
    __shared__ __align__(16) float As[128][36];
    __shared__ __align__(16) float Bs[32][132];
    int m0 = blockIdx.x * 128, j0 = blockIdx.y * 128, t = threadIdx.x;
    int w = t >> 5, wm = w >> 2, wn = w & 3;
    wmma::fragment<wmma::accumulator, 16, 16, 8, float> c[4][2];
    #pragma unroll
    for (int mi = 0; mi < 4; mi++)
        #pragma unroll
        for (int ni = 0; ni < 2; ni++) wmma::fill_fragment(c[mi][ni], 0.0f);
    for (int c0 = 0; c0 < 256; c0 += 32) {
        #pragma unroll
        for (int r = 0; r < 4; r++) {
            int i = t + 256 * r, row = i >> 3, kq = i & 7;
            int n = m0 + row;
            float cd = (float)(n >> 8)        * 0.0625f;
            float chc = (float)((n >> 4) & 15) * 0.0625f;
            float cw = (float)(n & 15)        * 0.0625f;
            int k = c0 + kq * 4;
            float4 wd = *(const float4*)&w1[k];
            float4 wh = *(const float4*)&w1[256 + k];
            float4 ww = *(const float4*)&w1[512 + k];
            float4 bb = *(const float4*)&b1[k];
            As[row][kq * 4 + 0] = wmma::__float_to_tf32(geluf(cd * wd.x + chc * wh.x + cw * ww.x + bb.x));
            As[row][kq * 4 + 1] = wmma::__float_to_tf32(geluf(cd * wd.y + chc * wh.y + cw * ww.y + bb.y));
            As[row][kq * 4 + 2] = wmma::__float_to_tf32(geluf(cd * wd.z + chc * wh.z + cw * ww.z + bb.z));
            As[row][kq * 4 + 3] = wmma::__float_to_tf32(geluf(cd * wd.w + chc * wh.w + cw * ww.w + bb.w));
        }
        #pragma unroll
        for (int r = 0; r < 4; r++) {
            int i = t + 256 * r, kk = i >> 5, nq = i & 31;
            float4 v = *(const float4*)&w2[(size_t)(c0 + kk) * 512 + j0 + nq * 4];
            Bs[kk][nq * 4 + 0] = wmma::__float_to_tf32(v.x);
            Bs[kk][nq * 4 + 1] = wmma::__float_to_tf32(v.y);
            Bs[kk][nq * 4 + 2] = wmma::__float_to_tf32(v.z);
            Bs[kk][nq * 4 + 3] = wmma::__float_to_tf32(v.w);
        }
        __syncthreads();
        #pragma unroll
        for (int kf = 0; kf < 4; kf++) {
            wmma::fragment<wmma::matrix_a, 16, 16, 8, wmma::precision::tf32, wmma::row_major> af[4];
            wmma::fragment<wmma::matrix_b, 16, 16, 8, wmma::precision::tf32, wmma::row_major> bf[2];
            #pragma unroll
            for (int mi = 0; mi < 4; mi++)
                wmma::load_matrix_sync(af[mi], &As[wm * 64 + mi * 16][kf * 8], 36);
            #pragma unroll
            for (int ni = 0; ni < 2; ni++)
                wmma::load_matrix_sync(bf[ni], &Bs[kf * 8][wn * 32 + ni * 16], 132);
            #pragma unroll
            for (int mi = 0; mi < 4; mi++)
                #pragma unroll
                for (int ni = 0; ni < 2; ni++)
                    wmma::mma_sync(c[mi][ni], af[mi], bf[ni], c[mi][ni]);
        }
        __syncthreads();
    }
    #pragma unroll
    for (int mi = 0; mi < 4; mi++)
        #pragma unroll
        for (int ni = 0; ni < 2; ni++)
            wmma::store_matrix_sync(&g_PE[(size_t)(m0 + wm * 64 + mi * 16) * 512 + j0 + wn * 32 + ni * 16],
                                    c[mi][ni], 512, wmma::mem_row_major);
}

// ---------------- K2: mol rmsnorm + Q projection (+bq) -----------------------------
__global__ void __launch_bounds__(256) k_molq(const float* __restrict__ mol,
                                              const float* __restrict__ wmol,
                                              const float* __restrict__ wq,
                                              const float* __restrict__ bq) {
    __shared__ float x_s[8][512];
    __shared__ float part[8][8][128];
    int row0 = blockIdx.x * 8, jb = blockIdx.y * 128;
    int t = threadIdx.x;
    int w = t >> 5, lane = t & 31;
    float vals[16]; float ss = 0.0f;
    #pragma unroll
    for (int i = 0; i < 16; i++) {
        float v = mol[(row0 + w) * 512 + lane + i * 32];
        vals[i] = v; ss += v * v;
    }
    #pragma unroll
    for (int o = 16; o; o >>= 1) ss += __shfl_xor_sync(0xffffffffu, ss, o);
    float rv = rsqrtf(ss * (1.0f / 512.0f) + EPSV);
    #pragma unroll
    for (int i = 0; i < 16; i++) {
        int m = lane + i * 32;
        float xn = vals[i] * rv * wmol[m];
        x_s[w][m] = xn;
        if (blockIdx.y == 0) g_MOLN[(row0 + w) * 512 + m] = xn;
    }
    __syncthreads();
    int tk = w, tj = lane, j = jb + tj * 4;
    float4 acc[8];
    #pragma unroll
    for (int r = 0; r < 8; r++) acc[r] = make_float4(0.f, 0.f, 0.f, 0.f);
    #pragma unroll 8
    for (int c = tk * 64; c < tk * 64 + 64; c++) {
        float4 w4 = *(const float4*)&wq[(size_t)c * 512 + j];
        #pragma unroll
        for (int r = 0; r < 8; r++) {
            float x = x_s[r][c];
            acc[r].x += x * w4.x; acc[r].y += x * w4.y;
            acc[r].z += x * w4.z; acc[r].w += x * w4.w;
        }
    }
    #pragma unroll
    for (int r = 0; r < 8; r++) *(float4*)&part[tk][r][tj * 4] = acc[r];
    __syncthreads();
    {
        int r = t >> 5, cq = t & 31, j2 = jb + cq * 4;
        float4 s = make_float4(0.f, 0.f, 0.f, 0.f);
        #pragma unroll
        for (int k2 = 0; k2 < 8; k2++) {
            float4 p = *(const float4*)&part[k2][r][cq * 4];
            s.x += p.x; s.y += p.y; s.z += p.z; s.w += p.w;
        }
        float4 bv = *(const float4*)&bq[j2];
        s.x += bv.x; s.y += bv.y; s.z += bv.z; s.w += bv.w;
        *(float4*)&g_Q[(row0 + r) * 512 + j2] = s;
    }
}

// ---------------- K3: tq' = 0.125*wp[c]*(q_h . Wk_h[c,:]) --------------------------
__global__ void __launch_bounds__(256) k_tq2(const float* __restrict__ wkv,
                                             const float* __restrict__ wp) {
    __shared__ float As[16][128];
    __shared__ float Bs[16][128];
    int h = blockIdx.x, c0b = blockIdx.y * 128, t = threadIdx.x;
    int tr = t >> 4, tc = t & 15;
    float acc[8][8];
    #pragma unroll
    for (int i = 0; i < 8; i++)
        #pragma unroll
        for (int j = 0; j < 8; j++) acc[i][j] = 0.f;
    for (int k0 = 0; k0 < 64; k0 += 16) {
        {
            int r = t >> 1, k8 = (t & 1) * 8;
            const float* src = &g_Q[r * 512 + h * 64 + k0 + k8];
            float4 a0 = *(const float4*)&src[0];
            float4 a1 = *(const float4*)&src[4];
            As[k8 + 0][r] = a0.x; As[k8 + 1][r] = a0.y; As[k8 + 2][r] = a0.z; As[k8 + 3][r] = a0.w;
            As[k8 + 4][r] = a1.x; As[k8 + 5][r] = a1.y; As[k8 + 6][r] = a1.z; As[k8 + 7][r] = a1.w;
        }
        {
            int c = t >> 1, k8 = (t & 1) * 8;
            const float* src = &wkv[(size_t)(c0b + c) * 1024 + h * 64 + k0 + k8];
            float4 v0 = *(const float4*)&src[0];
            float4 v1 = *(const float4*)&src[4];
            Bs[k8 + 0][c] = v0.x; Bs[k8 + 1][c] = v0.y; Bs[k8 + 2][c] = v0.z; Bs[k8 + 3][c] = v0.w;
            Bs[k8 + 4][c] = v1.x; Bs[k8 + 5][c] = v1.y; Bs[k8 + 6][c] = v1.z; Bs[k8 + 7][c] = v1.w;
        }
        __syncthreads();
        #pragma unroll
        for (int kk = 0; kk < 16; kk++) {
            float4 a0 = *(const float4*)&As[kk][tr * 8];
            float4 a1 = *(const float4*)&As[kk][tr * 8 + 4];
            float4 b0 = *(const float4*)&Bs[kk][tc * 8];
            float4 b1 = *(const float4*)&Bs[kk][tc * 8 + 4];
            float a[8] = {a0.x, a0.y, a0.z, a0.w, a1.x, a1.y, a1.z, a1.w};
            float bb[8] = {b0.x, b0.y, b0.z, b0.w, b1.x, b1.y, b1.z, b1.w};
            #pragma unroll
            for (int i = 0; i < 8; i++)
                #pragma unroll
                for (int j = 0; j < 8; j++) acc[i][j] += a[i] * bb[j];
        }
        __syncthreads();
    }
    float4 wp0 = *(const float4*)&wp[c0b + tc * 8];
    float4 wp1 = *(const float4*)&wp[c0b + tc * 8 + 4];
    float wpv[8] = {wp0.x, wp0.y, wp0.z, wp0.w, wp1.x, wp1.y, wp1.z, wp1.w};
    #pragma unroll
    for (int i = 0; i < 8; i++) {
        int r = tr * 8 + i, b = r >> 4, e = r & 15;
        float* dst = &g_TQ[(size_t)(b * 128 + h * 16 + e) * 256 + c0b + tc * 8];
        #pragma unroll
        for (int j = 0; j < 8; j++) dst[j] = acc[i][j] * wpv[j] * 0.125f;
    }
}

// ---------------- K4: scores (tf32 TC, fused): S = 0.125*q@PE^T + tq'@(X*rinv) -----
// Phase A: rinv for this n-tile. Phase B: per-head qpe directly into accumulators
// (each 16-row accumulator tile == one head; A/B fragments loaded straight from
// L2-resident g_Q / g_PE, ldm=512). Scale by 0.125, then the K=256 X mainloop.
__global__ void __launch_bounds__(256) k_scores_tc(const float* __restrict__ X) {
    __shared__ __align__(16) float As[128][36];
    __shared__ __align__(16) float Bs[32][132];
    __shared__ __align__(16) float rs[128];
    __shared__ float ss2[256];
    int n0 = blockIdx.x * 128, b = blockIdx.y, t = threadIdx.x;
    int w = t >> 5, wm = w >> 2, wn = w & 3;
    const float* Xb = X + (size_t)b * CC * NN;
    const float* TQ = g_TQ + (size_t)b * 128 * 256;
    float* Sb = g_S + (size_t)b * 128 * 4096;
    // phase A: rmsnorm rsqrt for this n-tile (also warms L2 with X)
    {
        int tn = t & 127, chh = t >> 7;
        const float* xp = Xb + (size_t)(chh * 128) * 4096 + n0 + tn;
        float s0 = 0.f, s1 = 0.f, s2 = 0.f, s3 = 0.f;
        #pragma unroll 4
        for (int c = 0; c < 128; c += 4) {
            float v0 = xp[(size_t)(c + 0) * 4096];
            float v1 = xp[(size_t)(c + 1) * 4096];
            float v2 = xp[(size_t)(c + 2) * 4096];
            float v3 = xp[(size_t)(c + 3) * 4096];
            s0 += v0 * v0; s1 += v1 * v1; s2 += v2 * v2; s3 += v3 * v3;
        }
        ss2[t] = (s0 + s1) + (s2 + s3);
    }
    __syncthreads();
    if (t < 128) {
        float rv = rsqrtf((ss2[t] + ss2[t + 128]) * (1.0f / 256.0f) + EPSV);
        rs[t] = rv;
        g_RINV[b * 4096 + n0 + t] = rv;
    }
    __syncthreads();
    wmma::fragment<wmma::accumulator, 16, 16, 8, float> c[4][2];
    #pragma unroll
    for (int mi = 0; mi < 4; mi++)
        #pragma unroll
        for (int ni = 0; ni < 2; ni++) wmma::fill_fragment(c[mi][ni], 0.0f);
    // phase B: qpe — per accumulator row-tile, h = wm*4+mi; gmem fragment loads
    #pragma unroll
    for (int mi = 0; mi < 4; mi++) {
        int h = wm * 4 + mi;
        const float* qbase  = &g_Q[(b * 16) * 512 + h * 64];
        const float* pebase = &g_PE[(size_t)(n0 + wn * 32) * 512 + h * 64];
        #pragma unroll
        for (int kf = 0; kf < 8; kf++) {
            wmma::fragment<wmma::matrix_a, 16, 16, 8, wmma::precision::tf32, wmma::row_major> af;
            wmma::load_matrix_sync(af, qbase + kf * 8, 512);
            #pragma unroll
            for (int e = 0; e < af.num_elements; e++) af.x[e] = wmma::__float_to_tf32(af.x[e]);
            #pragma unroll
            for (int ni = 0; ni < 2; ni++) {
                wmma::fragment<wmma::matrix_b, 16, 16, 8, wmma::precision::tf32, wmma::col_major> bf;
                wmma::load_matrix_sync(bf, pebase + (size_t)ni * 16 * 512 + kf * 8, 512);
                #pragma unroll
                for (int e = 0; e < bf.num_elements; e++) bf.x[e] = wmma::__float_to_tf32(bf.x[e]);
                wmma::mma_sync(c[mi][ni], af, bf, c[mi][ni]);
            }
        }
    }
    // fold the 0.125 attention scale into the qpe partial
    #pragma unroll
    for (int mi = 0; mi < 4; mi++)
        #pragma unroll
        for (int ni = 0; ni < 2; ni++)
            #pragma unroll
            for (int e = 0; e < c[mi][ni].num_elements; e++) c[mi][ni].x[e] *= 0.125f;
    // phase C: += tq' @ (X*rinv), K=256
    for (int c0 = 0; c0 < 256; c0 += 32) {
        #pragma unroll
        for (int r = 0; r < 4; r++) {
            int i = t + 256 * r, row = i >> 3, kq = i & 7;
            float4 v = *(const float4*)&TQ[(size_t)row * 256 + c0 + kq * 4];
            As[row][kq * 4 + 0] = wmma::__float_to_tf32(v.x);
            As[row][kq * 4 + 1] = wmma::__float_to_tf32(v.y);
            As[row][kq * 4 + 2] = wmma::__float_to_tf32(v.z);
            As[row][kq * 4 + 3] = wmma::__float_to_tf32(v.w);
        }
        #pragma unroll
        for (int r = 0; r < 4; r++) {
            int i = t + 256 * r, kk = i >> 5, nq = i & 31;
            float4 v = *(const float4*)&Xb[(size_t)(c0 + kk) * 4096 + n0 + nq * 4];
            Bs[kk][nq * 4 + 0] = wmma::__float_to_tf32(v.x * rs[nq * 4 + 0]);
            Bs[kk][nq * 4 + 1] = wmma::__float_to_tf32(v.y * rs[nq * 4 + 1]);
            Bs[kk][nq * 4 + 2] = wmma::__float_to_tf32(v.z * rs[nq * 4 + 2]);
            Bs[kk][nq * 4 + 3] = wmma::__float_to_tf32(v.w * rs[nq * 4 + 3]);
        }
        __syncthreads();
        #pragma unroll
        for (int kf = 0; kf < 4; kf++) {
            wmma::fragment<wmma::matrix_a, 16, 16, 8, wmma::precision::tf32, wmma::row_major> af[4];
            wmma::fragment<wmma::matrix_b, 16, 16, 8, wmma::precision::tf32, wmma::row_major> bf[2];
            #pragma unroll
            for (int mi = 0; mi < 4; mi++)
                wmma::load_matrix_sync(af[mi], &As[wm * 64 + mi * 16][kf * 8], 36);
            #pragma unroll
            for (int ni = 0; ni < 2; ni++)
                wmma::load_matrix_sync(bf[ni], &Bs[kf * 8][wn * 32 + ni * 16], 132);
            #pragma unroll
            for (int mi = 0; mi < 4; mi++)
                #pragma unroll
                for (int ni = 0; ni < 2; ni++)
                    wmma::mma_sync(c[mi][ni], af[mi], bf[ni], c[mi][ni]);
        }
        __syncthreads();
    }
    #pragma unroll
    for (int mi = 0; mi < 4; mi++)
        #pragma unroll
        for (int ni = 0; ni < 2; ni++)
            wmma::store_matrix_sync(&Sb[(size_t)(wm * 64 + mi * 16) * 4096 + n0 + wn * 32 + ni * 16],
                                    c[mi][ni], 4096, wmma::mem_row_major);
}

// ---------------- K5: softmax over n=4096 (512 thr) --------------------------------
__global__ void k_softmax() {
    __shared__ float red[32];
    int row = blockIdx.x;
    float* s = g_S + (size_t)row * NN;
    int t = threadIdx.x;  // 512
    float loc[8];
    float m = -1e30f;
    #pragma unroll
    for (int i = 0; i < 8; i++) { loc[i] = s[t + i * 512]; m = fmaxf(m, loc[i]); }
    m = blk_red<16, true>(m, red);
    float sum = 0.0f;
    #pragma unroll
    for (int i = 0; i < 8; i++) { loc[i] = __expf(loc[i] - m); sum += loc[i]; }
    sum = blk_red<16, false>(sum, red);
    float inv = 1.0f / sum;
    #pragma unroll
    for (int i = 0; i < 8; i++) s[t + i * 512] = loc[i] * inv;
}

// ---------------- K6: pa partials (tf32 TC): (p*rinv) @ X^T ------------------------
__global__ void __launch_bounds__(512) k_pa_tc(const float* __restrict__ X) {
    __shared__ __align__(16) float As[128][20];
    __shared__ __align__(16) float Bs[256][20];
    int ks = blockIdx.x, b = blockIdx.y, t = threadIdx.x;
    int nbase = ks * 256;
    int w = t >> 5, wm = w >> 3, wn = w & 7;
    const float* Xb = X + (size_t)b * CC * NN;
    wmma::fragment<wmma::accumulator, 16, 16, 8, float> c[4][2];
    #pragma unroll
    for (int mi = 0; mi < 4; mi++)
        #pragma unroll
        for (int ni = 0; ni < 2; ni++) wmma::fill_fragment(c[mi][ni], 0.0f);
    for (int k0 = 0; k0 < 256; k0 += 16) {
        {
            int row = t >> 2, kq = t & 3;
            int n = nbase + k0 + kq * 4;
            float4 p  = *(const float4*)&g_S[(size_t)(b * 128 + row) * 4096 + n];
            float4 rv = *(const float4*)&g_RINV[b * 4096 + n];
            As[row][kq * 4 + 0] = wmma::__float_to_tf32(p.x * rv.x);
            As[row][kq * 4 + 1] = wmma::__float_to_tf32(p.y * rv.y);
            As[row][kq * 4 + 2] = wmma::__float_to_tf32(p.z * rv.z);
            As[row][kq * 4 + 3] = wmma::__float_to_tf32(p.w * rv.w);
        }
        #pragma unroll
        for (int r = 0; r < 2; r++) {
            int i = t + 512 * r, cc = i >> 2, kq = i & 3;
            float4 v = *(const float4*)&Xb[(size_t)cc * 4096 + nbase + k0 + kq * 4];
            Bs[cc][kq * 4 + 0] = wmma::__float_to_tf32(v.x);
            Bs[cc][kq * 4 + 1] = wmma::__float_to_tf32(v.y);
            Bs[cc][kq * 4 + 2] = wmma::__float_to_tf32(v.z);
            Bs[cc][kq * 4 + 3] = wmma::__float_to_tf32(v.w);
        }
        __syncthreads();
        #pragma unroll
        for (int kf = 0; kf < 2; kf++) {
            wmma::fragment<wmma::matrix_a, 16, 16, 8, wmma::precision::tf32, wmma::row_major> af[4];
            wmma::fragment<wmma::matrix_b, 16, 16, 8, wmma::precision::tf32, wmma::col_major> bf[2];
            #pragma unroll
            for (int mi = 0; mi < 4; mi++)
                wmma::load_matrix_sync(af[mi], &As[wm * 64 + mi * 16][kf * 8], 20);
            #pragma unroll
            for (int ni = 0; ni < 2; ni++)
                wmma::load_matrix_sync(bf[ni], &Bs[wn * 32 + ni * 16][kf * 8], 20);
            #pragma unroll
            for (int mi = 0; mi < 4; mi++)
                #pragma unroll
                for (int ni = 0; ni < 2; ni++)
                    wmma::mma_sync(c[mi][ni], af[mi], bf[ni], c[mi][ni]);
        }
        __syncthreads();
    }
    #pragma unroll
    for (int mi = 0; mi < 4; mi++)
        #pragma unroll
        for (int ni = 0; ni < 2; ni++)
            wmma::store_matrix_sync(
                &g_PAP[(size_t)((ks * 8 + b) * 128 + wm * 64 + mi * 16) * 256 + wn * 32 + ni * 16],
                c[mi][ni], 256, wmma::mem_row_major);
}

// ---------------- K7: ope partials (tf32 TC): p @ (PE_h + bv + b2) ----------------
__global__ void __launch_bounds__(256) k_ppe_tc(const float* __restrict__ bkv,
                                                const float* __restrict__ peb2) {
    __shared__ __align__(16) float As[128][36];
    __shared__ __align__(16) float Bs[32][68];
    __shared__ float bias_s[64];
    int h = blockIdx.x, ks = blockIdx.y, t = threadIdx.x;
    int nb = ks * 512;
    int w = t >> 5, wm = w >> 1, wn = w & 1;
    if (t < 16) {
        float4 bv4 = *(const float4*)&bkv[512 + h * 64 + t * 4];
        float4 b24 = *(const float4*)&peb2[h * 64 + t * 4];
        bias_s[t * 4 + 0] = bv4.x + b24.x;
        bias_s[t * 4 + 1] = bv4.y + b24.y;
        bias_s[t * 4 + 2] = bv4.z + b24.z;
        bias_s[t * 4 + 3] = bv4.w + b24.w;
    }
    __syncthreads();
    wmma::fragment<wmma::accumulator, 16, 16, 8, float> c[2][2];
    #pragma unroll
    for (int mi = 0; mi < 2; mi++)
        #pragma unroll
        for (int ni = 0; ni < 2; ni++) wmma::fill_fragment(c[mi][ni], 0.0f);
    for (int k0 = 0; k0 < 512; k0 += 32) {
        #pragma unroll
        for (int r = 0; r < 4; r++) {
            int i = t + 256 * r, row = i >> 3, kq = i & 7;
            int b = row >> 4, e = row & 15;
            float4 v = *(const float4*)&g_S[(size_t)((b * 8 + h) * 16 + e) * 4096 + nb + k0 + kq * 4];
            As[row][kq * 4 + 0] = wmma::__float_to_tf32(v.x);
            As[row][kq * 4 + 1] = wmma::__float_to_tf32(v.y);
            As[row][kq * 4 + 2] = wmma::__float_to_tf32(v.z);
            As[row][kq * 4 + 3] = wmma::__float_to_tf32(v.w);
        }
        #pragma unroll
        for (int r = 0; r < 2; r++) {
            int i = t + 256 * r, kk = i >> 4, dq = i & 15;
            float4 v = *(const float4*)&g_PE[(size_t)(nb + k0 + kk) * 512 + h * 64 + dq * 4];
            Bs[kk][dq * 4 + 0] = wmma::__float_to_tf32(v.x + bias_s[dq * 4 + 0]);
            Bs[kk][dq * 4 + 1] = wmma::__float_to_tf32(v.y + bias_s[dq * 4 + 1]);
            Bs[kk][dq * 4 + 2] = wmma::__float_to_tf32(v.z + bias_s[dq * 4 + 2]);
            Bs[kk][dq * 4 + 3] = wmma::__float_to_tf32(v.w + bias_s[dq * 4 + 3]);
        }
        __syncthreads();
        #pragma unroll
        for (int kf = 0; kf < 4; kf++) {
            wmma::fragment<wmma::matrix_a, 16, 16, 8, wmma::precision::tf32, wmma::row_major> af[2];
            wmma::fragment<wmma::matrix_b, 16, 16, 8, wmma::precision::tf32, wmma::row_major> bf[2];
            #pragma unroll
            for (int mi = 0; mi < 2; mi++)
                wmma::load_matrix_sync(af[mi], &As[wm * 32 + mi * 16][kf * 8], 36);
            #pragma unroll
            for (int ni = 0; ni < 2; ni++)
                wmma::load_matrix_sync(bf[ni], &Bs[kf * 8][wn * 32 + ni * 16], 68);
            #pragma unroll
            for (int mi = 0; mi < 2; mi++)
                #pragma unroll
                for (int ni = 0; ni < 2; ni++)
                    wmma::mma_sync(c[mi][ni], af[mi], bf[ni], c[mi][ni]);
        }
        __syncthreads();
    }
    #pragma unroll
    for (int mi = 0; mi < 2; mi++)
        #pragma unroll
        for (int ni = 0; ni < 2; ni++)
            wmma::store_matrix_sync(
                &g_OPEP[(size_t)((ks * 8 + h) * 128 + wm * 32 + mi * 16) * 64 + wn * 32 + ni * 16],
                c[mi][ni], 64, wmma::mem_row_major);
}

// ---------------- K8: out0 = (pa*wp-reduced) @ Wv + ope ---------------------------
__global__ void __launch_bounds__(512) k_out(const float* __restrict__ wkv,
                                             const float* __restrict__ wp) {
    __shared__ float pool[8192];
    __shared__ float ope_s[4][512];
    int row0 = blockIdx.x * 4;
    int t = threadIdx.x;
    for (int idx = t; idx < 8192; idx += 512) {
        int r = idx >> 11, rest = idx & 2047, h = rest >> 8, c = rest & 255;
        int row = row0 + r, b = row >> 4, e = row & 15;
        float s = 0.f;
        #pragma unroll
        for (int ks = 0; ks < 16; ks++)
            s += g_PAP[(size_t)((ks * 8 + b) * 128 + h * 16 + e) * 256 + c];
        pool[idx] = s * wp[c];
    }
    for (int idx = t; idx < 2048; idx += 512) {
        int r = idx >> 9, j = idx & 511;
        int row = row0 + r, b = row >> 4, e = row & 15;
        int h = j >> 6, d = j & 63;
        float s = 0.f;
        #pragma unroll
        for (int ks = 0; ks < 8; ks++)
            s += g_OPEP[(size_t)((ks * 8 + h) * 128 + b * 16 + e) * 64 + d];
        ope_s[r][j] = s;
    }
    __syncthreads();
    int tj = t & 127, tk = t >> 7;
    int h = tj >> 4;
    float4 acc[4];
    #pragma unroll
    for (int r = 0; r < 4; r++) acc[r] = make_float4(0.f, 0.f, 0.f, 0.f);
    #pragma unroll 4
    for (int c = tk * 64; c < tk * 64 + 64; c++) {
        float4 w4 = *(const float4*)&wkv[(size_t)c * 1024 + 512 + tj * 4];
        #pragma unroll
        for (int r = 0; r < 4; r++) {
            float p = pool[r * 2048 + h * 256 + c];
            acc[r].x += p * w4.x; acc[r].y += p * w4.y;
            acc[r].z += p * w4.z; acc[r].w += p * w4.w;
        }
    }
    __syncthreads();
    #pragma unroll
    for (int r = 0; r < 4; r++) *(float4*)&pool[(tk * 4 + r) * 512 + tj * 4] = acc[r];
    __syncthreads();
    {
        int r = t >> 7, j0 = (t & 127) * 4;
        float4 s = make_float4(0.f, 0.f, 0.f, 0.f);
        #pragma unroll
        for (int k2 = 0; k2 < 4; k2++) {
            float4 p = *(const float4*)&pool[(k2 * 4 + r) * 512 + j0];
            s.x += p.x; s.y += p.y; s.z += p.z; s.w += p.w;
        }
        float4 op = *(const float4*)&ope_s[r][j0];
        s.x += op.x; s.y += op.y; s.z += op.z; s.w += op.w;
        *(float4*)&g_ATT0[(row0 + r) * 512 + j0] = s;
    }
}

// ---------------- K9: proj + residual ---------------------------------------------
__global__ void __launch_bounds__(256) k_proj(const float* __restrict__ wproj,
                                              const float* __restrict__ bproj) {
    __shared__ float x_s[8][512];
    __shared__ float part[8][8][128];
    int row0 = blockIdx.x * 8, jb = blockIdx.y * 128, t = threadIdx.x;
    for (int idx = t; idx < 4096; idx += 256)
        x_s[idx >> 9][idx & 511] = g_ATT0[(row0 + (idx >> 9)) * 512 + (idx & 511)];
    __syncthreads();
    int tk = t >> 5, tj = t & 31, j = jb + tj * 4;
    float4 acc[8];
    #pragma unroll
    for (int r = 0; r < 8; r++) acc[r] = make_float4(0.f, 0.f, 0.f, 0.f);
    #pragma unroll 8
    for (int c = tk * 64; c < tk * 64 + 64; c++) {
        float4 w4 = *(const float4*)&wproj[(size_t)c * 512 + j];
        #pragma unroll
        for (int r = 0; r < 8; r++) {
            float x = x_s[r][c];
            acc[r].x += x * w4.x; acc[r].y += x * w4.y;
            acc[r].z += x * w4.z; acc[r].w += x * w4.w;
        }
    }
    #pragma unroll
    for (int r = 0; r < 8; r++) *(float4*)&part[tk][r][tj * 4] = acc[r];
    __syncthreads();
    {
        int r = t >> 5, cq = t & 31, j2 = jb + cq * 4;
        float4 s = make_float4(0.f, 0.f, 0.f, 0.f);
        #pragma unroll
        for (int k2 = 0; k2 < 8; k2++) {
            float4 p = *(const float4*)&part[k2][r][cq * 4];
            s.x += p.x; s.y += p.y; s.z += p.z; s.w += p.w;
        }
        float4 bp = *(const float4*)&bproj[j2];
        float4 mn = *(const float4*)&g_MOLN[(row0 + r) * 512 + j2];
        s.x += bp.x + mn.x; s.y += bp.y + mn.y;
        s.z += bp.z + mn.z; s.w += bp.w + mn.w;
        *(float4*)&g_ATT[(row0 + r) * 512 + j2] = s;
    }
}

// ---------------- K10: ffn1 (fused rmsnorm) + gelu ----------------------------------
__global__ void __launch_bounds__(256) k_ffn1(const float* __restrict__ nw,
                                              const float* __restrict__ w1,
                                              const float* __restrict__ b1) {
    __shared__ float x_s[8][512];
    __shared__ float part[8][8][128];
    int row0 = blockIdx.x * 8, jb = blockIdx.y * 128, t = threadIdx.x;
    int w = t >> 5, lane = t & 31;
    {
        float vals[16]; float ss = 0.f;
        #pragma unroll
        for (int i = 0; i < 16; i++) {
            float v = g_ATT[(row0 + w) * 512 + lane + i * 32];
            vals[i] = v; ss += v * v;
        }
        #pragma unroll
        for (int o = 16; o; o >>= 1) ss += __shfl_xor_sync(0xffffffffu, ss, o);
        float rv = rsqrtf(ss * (1.0f / 512.0f) + EPSV);
        #pragma unroll
        for (int i = 0; i < 16; i++) {
            int m = lane + i * 32;
            x_s[w][m] = vals[i] * rv * nw[m];
        }
    }
    __syncthreads();
    int tk = t >> 5, tj = t & 31, j = jb + tj * 4;
    float4 acc[8];
    #pragma unroll
    for (int r = 0; r < 8; r++) acc[r] = make_float4(0.f, 0.f, 0.f, 0.f);
    #pragma unroll 8
    for (int c = tk * 64; c < tk * 64 + 64; c++) {
        float4 w4 = *(const float4*)&w1[(size_t)c * 2048 + j];
        #pragma unroll
        for (int r = 0; r < 8; r++) {
            float x = x_s[r][c];
            acc[r].x += x * w4.x; acc[r].y += x * w4.y;
            acc[r].z += x * w4.z; acc[r].w += x * w4.w;
        }
    }
    #pragma unroll
    for (int r = 0; r < 8; r++) *(float4*)&part[tk][r][tj * 4] = acc[r];
    __syncthreads();
    {
        int r = t >> 5, cq = t & 31, j2 = jb + cq * 4;
        float4 s = make_float4(0.f, 0.f, 0.f, 0.f);
        #pragma unroll
        for (int k2 = 0; k2 < 8; k2++) {
            float4 p = *(const float4*)&part[k2][r][cq * 4];
            s.x += p.x; s.y += p.y; s.z += p.z; s.w += p.w;
        }
        float4 bb = *(const float4*)&b1[j2];
        float4 o;
        o.x = geluf(s.x + bb.x); o.y = geluf(s.y + bb.y);
        o.z = geluf(s.z + bb.z); o.w = geluf(s.w + bb.w);
        *(float4*)&g_H1[(size_t)(row0 + r) * 2048 + j2] = o;
    }
}

// ---------------- K11: ffn2 + residual ----------------------------------------------
__global__ void __launch_bounds__(512) k_ffn2(const float* __restrict__ w2,
                                              const float* __restrict__ b2,
                                              float* __restrict__ out) {
    __shared__ float pool[8192];
    int row0 = blockIdx.x * 4, jb = blockIdx.y * 128, t = threadIdx.x;
    for (int idx = t; idx < 8192; idx += 512)
        pool[idx] = g_H1[(size_t)(row0 + (idx >> 11)) * 2048 + (idx & 2047)];
    __syncthreads();
    int tk = t >> 5, tj = t & 31, j = jb + tj * 4;
    float4 acc[4];
    #pragma unroll
    for (int r = 0; r < 4; r++) acc[r] = make_float4(0.f, 0.f, 0.f, 0.f);
    #pragma unroll 8
    for (int c = tk * 128; c < tk * 128 + 128; c++) {
        float4 w4 = *(const float4*)&w2[(size_t)c * 512 + j];
        #pragma unroll
        for (int r = 0; r < 4; r++) {
            float x = pool[r * 2048 + c];
            acc[r].x += x * w4.x; acc[r].y += x * w4.y;
            acc[r].z += x * w4.z; acc[r].w += x * w4.w;
        }
    }
    __syncthreads();
    #pragma unroll
    for (int r = 0; r < 4; r++) *(float4*)&pool[tk * 512 + r * 128 + tj * 4] = acc[r];
    __syncthreads();
    {
        int r = t >> 7, cq = t & 127;
        float s = 0.f;
        #pragma unroll
        for (int k2 = 0; k2 < 16; k2++) s += pool[k2 * 512 + r * 128 + cq];
        int j2 = jb + cq;
        out[(row0 + r) * 512 + j2] = s + b2[j2] + g_ATT[(row0 + r) * 512 + j2];
    }
}

// ---------------- launch -------------------------------------------------------------
extern "C" void kernel_launch(void* const* d_in, const int* in_sizes, int n_in,
                              void* d_out, int out_size) {
    const float* patch   = (const float*)d_in[0];
    const float* mol     = (const float*)d_in[1];
    const float* pe_w1   = (const float*)d_in[2];
    const float* pe_b1   = (const float*)d_in[3];
    const float* pe_w2   = (const float*)d_in[4];
    const float* pe_b2   = (const float*)d_in[5];
    const float* wq      = (const float*)d_in[6];
    const float* bq      = (const float*)d_in[7];
    const float* wkv     = (const float*)d_in[8];
    const float* bkv     = (const float*)d_in[9];
    const float* wproj   = (const float*)d_in[10];
    const float* bproj   = (const float*)d_in[11];
    const float* nmolw   = (const float*)d_in[12];
    const float* npatchw = (const float*)d_in[13];
    const float* ffn_w1  = (const float*)d_in[14];
    const float* ffn_b1  = (const float*)d_in[15];
    const float* ffn_w2  = (const float*)d_in[16];
    const float* ffn_b2  = (const float*)d_in[17];
    const float* ffn_nw  = (const float*)d_in[18];
    float* out = (float*)d_out;
    (void)in_sizes; (void)n_in; (void)out_size;

    k_peg_tc   <<<dim3(32, 4), 256>>>(pe_w1, pe_b1, pe_w2);
    k_molq     <<<dim3(16, 4), 256>>>(mol, nmolw, wq, bq);
    k_tq2      <<<dim3(8, 2), 256>>>(wkv, npatchw);
    k_scores_tc<<<dim3(32, 8), 256>>>(patch);
    k_softmax  <<<BB * 128, 512>>>();
    k_pa_tc    <<<dim3(16, 8), 512>>>(patch);
    k_ppe_tc   <<<dim3(8, 8), 256>>>(bkv, pe_b2);
    k_out      <<<32, 512>>>(wkv, npatchw);
    k_proj     <<<dim3(16, 4), 256>>>(wproj, bproj);
    k_ffn1     <<<dim3(16, 16), 256>>>(ffn_nw, ffn_w1, ffn_b1);
    k_ffn2     <<<dim3(32, 4), 512>>>(ffn_w2, ffn_b2, out);
}

// round 15
// speedup vs baseline: 1.0244x; 1.0244x over previous
#include <cuda_runtime.h>
#include <mma.h>
#include <math.h>

using namespace nvcuda;

#define BB 8
#define CC 256
#define NN 4096
#define MM 512
#define EE 16
#define NH 8
#define FFNH 2048
#define EPSV 1.1920929e-07f

// ------------- scratch (__device__ globals; no allocation allowed) ---------------
__device__ float g_PE  [NN * MM];             // pos_enc G@W2 (NO bias)
__device__ float g_RINV[BB * NN];             // patch rmsnorm rsqrt (written by k_scores_tc)
__device__ float g_Q   [128 * 512];           // q rows=(b,e) (includes bq)
__device__ float g_MOLN[128 * 512];           // normalized mol (residual)
__device__ float g_TQ  [BB * 128 * 256];      // tq' rows=(b, h*16+e), wp & 0.125 folded
__device__ float g_S   [(size_t)BB * 128 * NN];       // scores/probs  16.8 MB
__device__ float g_PAP [(size_t)16 * BB * 128 * 256]; // pa partials   16.8 MB
__device__ float g_OPEP[8 * 8 * 128 * 64];    // p@(pe+bv+b2) partials
__device__ float g_ATT0[128 * 512];           // attention out (pre-proj)
__device__ float g_ATT [128 * 512];           // attended (post residual)
__device__ float g_H1  [128 * 2048];          // ffn hidden

__device__ __forceinline__ float geluf(float x) {
    return 0.5f * x * (1.0f + erff(x * 0.70710678118654752440f));
}

template <int NWARPS, bool DOMAX>
__device__ __forceinline__ float blk_red(float v, float* red) {
    #pragma unroll
    for (int o = 16; o; o >>= 1) {
        float t = __shfl_xor_sync(0xffffffffu, v, o);
        v = DOMAX ? fmaxf(v, t) : v + t;
    }
    if ((threadIdx.x & 31) == 0) red[threadIdx.x >> 5] = v;
    __syncthreads();
    if (threadIdx.x < 32) {
        float r = (threadIdx.x < NWARPS) ? red[threadIdx.x] : (DOMAX ? -1e30f : 0.0f);
        #pragma unroll
        for (int o = NWARPS >> 1; o; o >>= 1) {
            float t = __shfl_xor_sync(0xffffffffu, r, o);
            r = DOMAX ? fmaxf(r, t) : r + t;
        }
        if (threadIdx.x == 0) red[0] = r;
    }
    __syncthreads();
    float s = red[0];
    __syncthreads();
    return s;
}

// ---------------- K1: PE = gelu(coords@W1+b1) @ W2 (tf32 TC, gelu fused) -----------
__global__ void __launch_bounds__(256) k_peg_tc(const float* __restrict__ w1,
                                                const float* __restrict__ b1,
                                                const float* __restrict__ w2) {
    __shared__ __align__(16) float As[128][36];
    __shared__ __align__(16) float Bs[32][132];
    int m0 = blockIdx.x * 128, j0 = blockIdx.y * 128, t = threadIdx.x;
    int w = t >> 5, wm = w >> 2, wn = w & 3;
    wmma::fragment<wmma::accumulator, 16, 16, 8, float> c[4][2];
    #pragma unroll
    for (int mi = 0; mi < 4; mi++)
        #pragma unroll
        for (int ni = 0; ni < 2; ni++) wmma::fill_fragment(c[mi][ni], 0.0f);
    for (int c0 = 0; c0 < 256; c0 += 32) {
        #pragma unroll
        for (int r = 0; r < 4; r++) {
            int i = t + 256 * r, row = i >> 3, kq = i & 7;
            int n = m0 + row;
            float cd = (float)(n >> 8)        * 0.0625f;
            float chc = (float)((n >> 4) & 15) * 0.0625f;
            float cw = (float)(n & 15)        * 0.0625f;
            int k = c0 + kq * 4;
            float4 wd = *(const float4*)&w1[k];
            float4 wh = *(const float4*)&w1[256 + k];
            float4 ww = *(const float4*)&w1[512 + k];
            float4 bb = *(const float4*)&b1[k];
            As[row][kq * 4 + 0] = wmma::__float_to_tf32(geluf(cd * wd.x + chc * wh.x + cw * ww.x + bb.x));
            As[row][kq * 4 + 1] = wmma::__float_to_tf32(geluf(cd * wd.y + chc * wh.y + cw * ww.y + bb.y));
            As[row][kq * 4 + 2] = wmma::__float_to_tf32(geluf(cd * wd.z + chc * wh.z + cw * ww.z + bb.z));
            As[row][kq * 4 + 3] = wmma::__float_to_tf32(geluf(cd * wd.w + chc * wh.w + cw * ww.w + bb.w));
        }
        #pragma unroll
        for (int r = 0; r < 4; r++) {
            int i = t + 256 * r, kk = i >> 5, nq = i & 31;
            float4 v = *(const float4*)&w2[(size_t)(c0 + kk) * 512 + j0 + nq * 4];
            Bs[kk][nq * 4 + 0] = wmma::__float_to_tf32(v.x);
            Bs[kk][nq * 4 + 1] = wmma::__float_to_tf32(v.y);
            Bs[kk][nq * 4 + 2] = wmma::__float_to_tf32(v.z);
            Bs[kk][nq * 4 + 3] = wmma::__float_to_tf32(v.w);
        }
        __syncthreads();
        #pragma unroll
        for (int kf = 0; kf < 4; kf++) {
            wmma::fragment<wmma::matrix_a, 16, 16, 8, wmma::precision::tf32, wmma::row_major> af[4];
            wmma::fragment<wmma::matrix_b, 16, 16, 8, wmma::precision::tf32, wmma::row_major> bf[2];
            #pragma unroll
            for (int mi = 0; mi < 4; mi++)
                wmma::load_matrix_sync(af[mi], &As[wm * 64 + mi * 16][kf * 8], 36);
            #pragma unroll
            for (int ni = 0; ni < 2; ni++)
                wmma::load_matrix_sync(bf[ni], &Bs[kf * 8][wn * 32 + ni * 16], 132);
            #pragma unroll
            for (int mi = 0; mi < 4; mi++)
                #pragma unroll
                for (int ni = 0; ni < 2; ni++)
                    wmma::mma_sync(c[mi][ni], af[mi], bf[ni], c[mi][ni]);
        }
        __syncthreads();
    }
    #pragma unroll
    for (int mi = 0; mi < 4; mi++)
        #pragma unroll
        for (int ni = 0; ni < 2; ni++)
            wmma::store_matrix_sync(&g_PE[(size_t)(m0 + wm * 64 + mi * 16) * 512 + j0 + wn * 32 + ni * 16],
                                    c[mi][ni], 512, wmma::mem_row_major);
}

// ---------------- K2: mol rmsnorm + Q projection (+bq) -----------------------------
__global__ void __launch_bounds__(256) k_molq(const float* __restrict__ mol,
                                              const float* __restrict__ wmol,
                                              const float* __restrict__ wq,
                                              const float* __restrict__ bq) {
    __shared__ float x_s[8][512];
    __shared__ float part[8][8][128];
    int row0 = blockIdx.x * 8, jb = blockIdx.y * 128;
    int t = threadIdx.x;
    int w = t >> 5, lane = t & 31;
    float vals[16]; float ss = 0.0f;
    #pragma unroll
    for (int i = 0; i < 16; i++) {
        float v = mol[(row0 + w) * 512 + lane + i * 32];
        vals[i] = v; ss += v * v;
    }
    #pragma unroll
    for (int o = 16; o; o >>= 1) ss += __shfl_xor_sync(0xffffffffu, ss, o);
    float rv = rsqrtf(ss * (1.0f / 512.0f) + EPSV);
    #pragma unroll
    for (int i = 0; i < 16; i++) {
        int m = lane + i * 32;
        float xn = vals[i] * rv * wmol[m];
        x_s[w][m] = xn;
        if (blockIdx.y == 0) g_MOLN[(row0 + w) * 512 + m] = xn;
    }
    __syncthreads();
    int tk = w, tj = lane, j = jb + tj * 4;
    float4 acc[8];
    #pragma unroll
    for (int r = 0; r < 8; r++) acc[r] = make_float4(0.f, 0.f, 0.f, 0.f);
    #pragma unroll 8
    for (int c = tk * 64; c < tk * 64 + 64; c++) {
        float4 w4 = *(const float4*)&wq[(size_t)c * 512 + j];
        #pragma unroll
        for (int r = 0; r < 8; r++) {
            float x = x_s[r][c];
            acc[r].x += x * w4.x; acc[r].y += x * w4.y;
            acc[r].z += x * w4.z; acc[r].w += x * w4.w;
        }
    }
    #pragma unroll
    for (int r = 0; r < 8; r++) *(float4*)&part[tk][r][tj * 4] = acc[r];
    __syncthreads();
    {
        int r = t >> 5, cq = t & 31, j2 = jb + cq * 4;
        float4 s = make_float4(0.f, 0.f, 0.f, 0.f);
        #pragma unroll
        for (int k2 = 0; k2 < 8; k2++) {
            float4 p = *(const float4*)&part[k2][r][cq * 4];
            s.x += p.x; s.y += p.y; s.z += p.z; s.w += p.w;
        }
        float4 bv = *(const float4*)&bq[j2];
        s.x += bv.x; s.y += bv.y; s.z += bv.z; s.w += bv.w;
        *(float4*)&g_Q[(row0 + r) * 512 + j2] = s;
    }
}

// ---------------- K3: tq' = 0.125*wp[c]*(q_h . Wk_h[c,:]) --------------------------
__global__ void __launch_bounds__(256) k_tq2(const float* __restrict__ wkv,
                                             const float* __restrict__ wp) {
    __shared__ float As[16][128];
    __shared__ float Bs[16][128];
    int h = blockIdx.x, c0b = blockIdx.y * 128, t = threadIdx.x;
    int tr = t >> 4, tc = t & 15;
    float acc[8][8];
    #pragma unroll
    for (int i = 0; i < 8; i++)
        #pragma unroll
        for (int j = 0; j < 8; j++) acc[i][j] = 0.f;
    for (int k0 = 0; k0 < 64; k0 += 16) {
        {
            int r = t >> 1, k8 = (t & 1) * 8;
            const float* src = &g_Q[r * 512 + h * 64 + k0 + k8];
            float4 a0 = *(const float4*)&src[0];
            float4 a1 = *(const float4*)&src[4];
            As[k8 + 0][r] = a0.x; As[k8 + 1][r] = a0.y; As[k8 + 2][r] = a0.z; As[k8 + 3][r] = a0.w;
            As[k8 + 4][r] = a1.x; As[k8 + 5][r] = a1.y; As[k8 + 6][r] = a1.z; As[k8 + 7][r] = a1.w;
        }
        {
            int c = t >> 1, k8 = (t & 1) * 8;
            const float* src = &wkv[(size_t)(c0b + c) * 1024 + h * 64 + k0 + k8];
            float4 v0 = *(const float4*)&src[0];
            float4 v1 = *(const float4*)&src[4];
            Bs[k8 + 0][c] = v0.x; Bs[k8 + 1][c] = v0.y; Bs[k8 + 2][c] = v0.z; Bs[k8 + 3][c] = v0.w;
            Bs[k8 + 4][c] = v1.x; Bs[k8 + 5][c] = v1.y; Bs[k8 + 6][c] = v1.z; Bs[k8 + 7][c] = v1.w;
        }
        __syncthreads();
        #pragma unroll
        for (int kk = 0; kk < 16; kk++) {
            float4 a0 = *(const float4*)&As[kk][tr * 8];
            float4 a1 = *(const float4*)&As[kk][tr * 8 + 4];
            float4 b0 = *(const float4*)&Bs[kk][tc * 8];
            float4 b1 = *(const float4*)&Bs[kk][tc * 8 + 4];
            float a[8] = {a0.x, a0.y, a0.z, a0.w, a1.x, a1.y, a1.z, a1.w};
            float bb[8] = {b0.x, b0.y, b0.z, b0.w, b1.x, b1.y, b1.z, b1.w};
            #pragma unroll
            for (int i = 0; i < 8; i++)
                #pragma unroll
                for (int j = 0; j < 8; j++) acc[i][j] += a[i] * bb[j];
        }
        __syncthreads();
    }
    float4 wp0 = *(const float4*)&wp[c0b + tc * 8];
    float4 wp1 = *(const float4*)&wp[c0b + tc * 8 + 4];
    float wpv[8] = {wp0.x, wp0.y, wp0.z, wp0.w, wp1.x, wp1.y, wp1.z, wp1.w};
    #pragma unroll
    for (int i = 0; i < 8; i++) {
        int r = tr * 8 + i, b = r >> 4, e = r & 15;
        float* dst = &g_TQ[(size_t)(b * 128 + h * 16 + e) * 256 + c0b + tc * 8];
        #pragma unroll
        for (int j = 0; j < 8; j++) dst[j] = acc[i][j] * wpv[j] * 0.125f;
    }
}

// ---------------- K4: S = (0.125*q_h) @ PE_h^T  (tf32 TC, K=64, col-major B) -------
__global__ void __launch_bounds__(256) k_qpe_tc() {
    __shared__ __align__(16) float As[128][36];
    __shared__ __align__(16) float Bs[128][36];
    int n0 = blockIdx.x * 128, h = blockIdx.y, t = threadIdx.x;
    int w = t >> 5, wm = w >> 2, wn = w & 3;
    wmma::fragment<wmma::accumulator, 16, 16, 8, float> c[4][2];
    #pragma unroll
    for (int mi = 0; mi < 4; mi++)
        #pragma unroll
        for (int ni = 0; ni < 2; ni++) wmma::fill_fragment(c[mi][ni], 0.0f);
    for (int c0 = 0; c0 < 64; c0 += 32) {
        #pragma unroll
        for (int r = 0; r < 4; r++) {
            int i = t + 256 * r, row = i >> 3, kq = i & 7;
            float4 v = *(const float4*)&g_Q[row * 512 + h * 64 + c0 + kq * 4];
            As[row][kq * 4 + 0] = wmma::__float_to_tf32(0.125f * v.x);
            As[row][kq * 4 + 1] = wmma::__float_to_tf32(0.125f * v.y);
            As[row][kq * 4 + 2] = wmma::__float_to_tf32(0.125f * v.z);
            As[row][kq * 4 + 3] = wmma::__float_to_tf32(0.125f * v.w);
        }
        #pragma unroll
        for (int r = 0; r < 4; r++) {
            int i = t + 256 * r, row = i >> 3, kq = i & 7;
            float4 v = *(const float4*)&g_PE[(size_t)(n0 + row) * 512 + h * 64 + c0 + kq * 4];
            Bs[row][kq * 4 + 0] = wmma::__float_to_tf32(v.x);
            Bs[row][kq * 4 + 1] = wmma::__float_to_tf32(v.y);
            Bs[row][kq * 4 + 2] = wmma::__float_to_tf32(v.z);
            Bs[row][kq * 4 + 3] = wmma::__float_to_tf32(v.w);
        }
        __syncthreads();
        #pragma unroll
        for (int kf = 0; kf < 4; kf++) {
            wmma::fragment<wmma::matrix_a, 16, 16, 8, wmma::precision::tf32, wmma::row_major> af[4];
            wmma::fragment<wmma::matrix_b, 16, 16, 8, wmma::precision::tf32, wmma::col_major> bf[2];
            #pragma unroll
            for (int mi = 0; mi < 4; mi++)
                wmma::load_matrix_sync(af[mi], &As[wm * 64 + mi * 16][kf * 8], 36);
            #pragma unroll
            for (int ni = 0; ni < 2; ni++)
                wmma::load_matrix_sync(bf[ni], &Bs[wn * 32 + ni * 16][kf * 8], 36);
            #pragma unroll
            for (int mi = 0; mi < 4; mi++)
                #pragma unroll
                for (int ni = 0; ni < 2; ni++)
                    wmma::mma_sync(c[mi][ni], af[mi], bf[ni], c[mi][ni]);
        }
        __syncthreads();
    }
    #pragma unroll
    for (int mi = 0; mi < 4; mi++) {
        int r0 = wm * 64 + mi * 16;
        int b = r0 >> 4;
        float* dst = &g_S[(size_t)((b * 8 + h) * 16) * 4096 + n0 + wn * 32];
        #pragma unroll
        for (int ni = 0; ni < 2; ni++)
            wmma::store_matrix_sync(dst + ni * 16, c[mi][ni], 4096, wmma::mem_row_major);
    }
}

// ---------------- K5: scores (tf32 TC, rinv fused): S += tq' @ (X*rinv) ------------
__global__ void __launch_bounds__(256) k_scores_tc(const float* __restrict__ X) {
    __shared__ __align__(16) float As[128][36];
    __shared__ __align__(16) float Bs[32][132];
    __shared__ __align__(16) float rs[128];
    __shared__ float ss2[256];
    int n0 = blockIdx.x * 128, b = blockIdx.y, t = threadIdx.x;
    int w = t >> 5, wm = w >> 2, wn = w & 3;
    const float* Xb = X + (size_t)b * CC * NN;
    const float* TQ = g_TQ + (size_t)b * 128 * 256;
    float* Sb = g_S + (size_t)b * 128 * 4096;
    {
        int tn = t & 127, chh = t >> 7;
        const float* xp = Xb + (size_t)(chh * 128) * 4096 + n0 + tn;
        float s0 = 0.f, s1 = 0.f, s2 = 0.f, s3 = 0.f;
        #pragma unroll 4
        for (int c = 0; c < 128; c += 4) {
            float v0 = xp[(size_t)(c + 0) * 4096];
            float v1 = xp[(size_t)(c + 1) * 4096];
            float v2 = xp[(size_t)(c + 2) * 4096];
            float v3 = xp[(size_t)(c + 3) * 4096];
            s0 += v0 * v0; s1 += v1 * v1; s2 += v2 * v2; s3 += v3 * v3;
        }
        ss2[t] = (s0 + s1) + (s2 + s3);
    }
    __syncthreads();
    if (t < 128) {
        float rv = rsqrtf((ss2[t] + ss2[t + 128]) * (1.0f / 256.0f) + EPSV);
        rs[t] = rv;
        g_RINV[b * 4096 + n0 + t] = rv;
    }
    __syncthreads();
    wmma::fragment<wmma::accumulator, 16, 16, 8, float> c[4][2];
    #pragma unroll
    for (int mi = 0; mi < 4; mi++)
        #pragma unroll
        for (int ni = 0; ni < 2; ni++)
            wmma::load_matrix_sync(c[mi][ni],
                &Sb[(size_t)(wm * 64 + mi * 16) * 4096 + n0 + wn * 32 + ni * 16],
                4096, wmma::mem_row_major);
    for (int c0 = 0; c0 < 256; c0 += 32) {
        #pragma unroll
        for (int r = 0; r < 4; r++) {
            int i = t + 256 * r, row = i >> 3, kq = i & 7;
            float4 v = *(const float4*)&TQ[(size_t)row * 256 + c0 + kq * 4];
            As[row][kq * 4 + 0] = wmma::__float_to_tf32(v.x);
            As[row][kq * 4 + 1] = wmma::__float_to_tf32(v.y);
            As[row][kq * 4 + 2] = wmma::__float_to_tf32(v.z);
            As[row][kq * 4 + 3] = wmma::__float_to_tf32(v.w);
        }
        #pragma unroll
        for (int r = 0; r < 4; r++) {
            int i = t + 256 * r, kk = i >> 5, nq = i & 31;
            float4 v = *(const float4*)&Xb[(size_t)(c0 + kk) * 4096 + n0 + nq * 4];
            Bs[kk][nq * 4 + 0] = wmma::__float_to_tf32(v.x * rs[nq * 4 + 0]);
            Bs[kk][nq * 4 + 1] = wmma::__float_to_tf32(v.y * rs[nq * 4 + 1]);
            Bs[kk][nq * 4 + 2] = wmma::__float_to_tf32(v.z * rs[nq * 4 + 2]);
            Bs[kk][nq * 4 + 3] = wmma::__float_to_tf32(v.w * rs[nq * 4 + 3]);
        }
        __syncthreads();
        #pragma unroll
        for (int kf = 0; kf < 4; kf++) {
            wmma::fragment<wmma::matrix_a, 16, 16, 8, wmma::precision::tf32, wmma::row_major> af[4];
            wmma::fragment<wmma::matrix_b, 16, 16, 8, wmma::precision::tf32, wmma::row_major> bf[2];
            #pragma unroll
            for (int mi = 0; mi < 4; mi++)
                wmma::load_matrix_sync(af[mi], &As[wm * 64 + mi * 16][kf * 8], 36);
            #pragma unroll
            for (int ni = 0; ni < 2; ni++)
                wmma::load_matrix_sync(bf[ni], &Bs[kf * 8][wn * 32 + ni * 16], 132);
            #pragma unroll
            for (int mi = 0; mi < 4; mi++)
                #pragma unroll
                for (int ni = 0; ni < 2; ni++)
                    wmma::mma_sync(c[mi][ni], af[mi], bf[ni], c[mi][ni]);
        }
        __syncthreads();
    }
    #pragma unroll
    for (int mi = 0; mi < 4; mi++)
        #pragma unroll
        for (int ni = 0; ni < 2; ni++)
            wmma::store_matrix_sync(&Sb[(size_t)(wm * 64 + mi * 16) * 4096 + n0 + wn * 32 + ni * 16],
                                    c[mi][ni], 4096, wmma::mem_row_major);
}

// ---------------- K6: softmax over n=4096 (512 thr) --------------------------------
__global__ void k_softmax() {
    __shared__ float red[32];
    int row = blockIdx.x;
    float* s = g_S + (size_t)row * NN;
    int t = threadIdx.x;  // 512
    float loc[8];
    float m = -1e30f;
    #pragma unroll
    for (int i = 0; i < 8; i++) { loc[i] = s[t + i * 512]; m = fmaxf(m, loc[i]); }
    m = blk_red<16, true>(m, red);
    float sum = 0.0f;
    #pragma unroll
    for (int i = 0; i < 8; i++) { loc[i] = __expf(loc[i] - m); sum += loc[i]; }
    sum = blk_red<16, false>(sum, red);
    float inv = 1.0f / sum;
    #pragma unroll
    for (int i = 0; i < 8; i++) s[t + i * 512] = loc[i] * inv;
}

// ---------------- K7: pa partials (tf32 TC): (p*rinv) @ X^T, K-step 16 -------------
__global__ void __launch_bounds__(512) k_pa_tc(const float* __restrict__ X) {
    __shared__ __align__(16) float As[128][20];
    __shared__ __align__(16) float Bs[256][20];
    int ks = blockIdx.x, b = blockIdx.y, t = threadIdx.x;
    int nbase = ks * 256;
    int w = t >> 5, wm = w >> 3, wn = w & 7;
    const float* Xb = X + (size_t)b * CC * NN;
    wmma::fragment<wmma::accumulator, 16, 16, 8, float> c[4][2];
    #pragma unroll
    for (int mi = 0; mi < 4; mi++)
        #pragma unroll
        for (int ni = 0; ni < 2; ni++) wmma::fill_fragment(c[mi][ni], 0.0f);
    for (int k0 = 0; k0 < 256; k0 += 16) {
        {
            int row = t >> 2, kq = t & 3;
            int n = nbase + k0 + kq * 4;
            float4 p  = *(const float4*)&g_S[(size_t)(b * 128 + row) * 4096 + n];
            float4 rv = *(const float4*)&g_RINV[b * 4096 + n];
            As[row][kq * 4 + 0] = wmma::__float_to_tf32(p.x * rv.x);
            As[row][kq * 4 + 1] = wmma::__float_to_tf32(p.y * rv.y);
            As[row][kq * 4 + 2] = wmma::__float_to_tf32(p.z * rv.z);
            As[row][kq * 4 + 3] = wmma::__float_to_tf32(p.w * rv.w);
        }
        #pragma unroll
        for (int r = 0; r < 2; r++) {
            int i = t + 512 * r, cc = i >> 2, kq = i & 3;
            float4 v = *(const float4*)&Xb[(size_t)cc * 4096 + nbase + k0 + kq * 4];
            Bs[cc][kq * 4 + 0] = wmma::__float_to_tf32(v.x);
            Bs[cc][kq * 4 + 1] = wmma::__float_to_tf32(v.y);
            Bs[cc][kq * 4 + 2] = wmma::__float_to_tf32(v.z);
            Bs[cc][kq * 4 + 3] = wmma::__float_to_tf32(v.w);
        }
        __syncthreads();
        #pragma unroll
        for (int kf = 0; kf < 2; kf++) {
            wmma::fragment<wmma::matrix_a, 16, 16, 8, wmma::precision::tf32, wmma::row_major> af[4];
            wmma::fragment<wmma::matrix_b, 16, 16, 8, wmma::precision::tf32, wmma::col_major> bf[2];
            #pragma unroll
            for (int mi = 0; mi < 4; mi++)
                wmma::load_matrix_sync(af[mi], &As[wm * 64 + mi * 16][kf * 8], 20);
            #pragma unroll
            for (int ni = 0; ni < 2; ni++)
                wmma::load_matrix_sync(bf[ni], &Bs[wn * 32 + ni * 16][kf * 8], 20);
            #pragma unroll
            for (int mi = 0; mi < 4; mi++)
                #pragma unroll
                for (int ni = 0; ni < 2; ni++)
                    wmma::mma_sync(c[mi][ni], af[mi], bf[ni], c[mi][ni]);
        }
        __syncthreads();
    }
    #pragma unroll
    for (int mi = 0; mi < 4; mi++)
        #pragma unroll
        for (int ni = 0; ni < 2; ni++)
            wmma::store_matrix_sync(
                &g_PAP[(size_t)((ks * 8 + b) * 128 + wm * 64 + mi * 16) * 256 + wn * 32 + ni * 16],
                c[mi][ni], 256, wmma::mem_row_major);
}

// ---------------- K8: ope partials (tf32 TC): p @ (PE_h + bv + b2) ----------------
__global__ void __launch_bounds__(256) k_ppe_tc(const float* __restrict__ bkv,
                                                const float* __restrict__ peb2) {
    __shared__ __align__(16) float As[128][36];
    __shared__ __align__(16) float Bs[32][68];
    __shared__ float bias_s[64];
    int h = blockIdx.x, ks = blockIdx.y, t = threadIdx.x;
    int nb = ks * 512;
    int w = t >> 5, wm = w >> 1, wn = w & 1;
    if (t < 16) {
        float4 bv4 = *(const float4*)&bkv[512 + h * 64 + t * 4];
        float4 b24 = *(const float4*)&peb2[h * 64 + t * 4];
        bias_s[t * 4 + 0] = bv4.x + b24.x;
        bias_s[t * 4 + 1] = bv4.y + b24.y;
        bias_s[t * 4 + 2] = bv4.z + b24.z;
        bias_s[t * 4 + 3] = bv4.w + b24.w;
    }
    __syncthreads();
    wmma::fragment<wmma::accumulator, 16, 16, 8, float> c[2][2];
    #pragma unroll
    for (int mi = 0; mi < 2; mi++)
        #pragma unroll
        for (int ni = 0; ni < 2; ni++) wmma::fill_fragment(c[mi][ni], 0.0f);
    for (int k0 = 0; k0 < 512; k0 += 32) {
        #pragma unroll
        for (int r = 0; r < 4; r++) {
            int i = t + 256 * r, row = i >> 3, kq = i & 7;
            int b = row >> 4, e = row & 15;
            float4 v = *(const float4*)&g_S[(size_t)((b * 8 + h) * 16 + e) * 4096 + nb + k0 + kq * 4];
            As[row][kq * 4 + 0] = wmma::__float_to_tf32(v.x);
            As[row][kq * 4 + 1] = wmma::__float_to_tf32(v.y);
            As[row][kq * 4 + 2] = wmma::__float_to_tf32(v.z);
            As[row][kq * 4 + 3] = wmma::__float_to_tf32(v.w);
        }
        #pragma unroll
        for (int r = 0; r < 2; r++) {
            int i = t + 256 * r, kk = i >> 4, dq = i & 15;
            float4 v = *(const float4*)&g_PE[(size_t)(nb + k0 + kk) * 512 + h * 64 + dq * 4];
            Bs[kk][dq * 4 + 0] = wmma::__float_to_tf32(v.x + bias_s[dq * 4 + 0]);
            Bs[kk][dq * 4 + 1] = wmma::__float_to_tf32(v.y + bias_s[dq * 4 + 1]);
            Bs[kk][dq * 4 + 2] = wmma::__float_to_tf32(v.z + bias_s[dq * 4 + 2]);
            Bs[kk][dq * 4 + 3] = wmma::__float_to_tf32(v.w + bias_s[dq * 4 + 3]);
        }
        __syncthreads();
        #pragma unroll
        for (int kf = 0; kf < 4; kf++) {
            wmma::fragment<wmma::matrix_a, 16, 16, 8, wmma::precision::tf32, wmma::row_major> af[2];
            wmma::fragment<wmma::matrix_b, 16, 16, 8, wmma::precision::tf32, wmma::row_major> bf[2];
            #pragma unroll
            for (int mi = 0; mi < 2; mi++)
                wmma::load_matrix_sync(af[mi], &As[wm * 32 + mi * 16][kf * 8], 36);
            #pragma unroll
            for (int ni = 0; ni < 2; ni++)
                wmma::load_matrix_sync(bf[ni], &Bs[kf * 8][wn * 32 + ni * 16], 68);
            #pragma unroll
            for (int mi = 0; mi < 2; mi++)
                #pragma unroll
                for (int ni = 0; ni < 2; ni++)
                    wmma::mma_sync(c[mi][ni], af[mi], bf[ni], c[mi][ni]);
        }
        __syncthreads();
    }
    #pragma unroll
    for (int mi = 0; mi < 2; mi++)
        #pragma unroll
        for (int ni = 0; ni < 2; ni++)
            wmma::store_matrix_sync(
                &g_OPEP[(size_t)((ks * 8 + h) * 128 + wm * 32 + mi * 16) * 64 + wn * 32 + ni * 16],
                c[mi][ni], 64, wmma::mem_row_major);
}

// ---------------- K9: out0 = (pa*wp-reduced) @ Wv + ope ---------------------------
__global__ void __launch_bounds__(512) k_out(const float* __restrict__ wkv,
                                             const float* __restrict__ wp) {
    __shared__ float pool[8192];
    __shared__ float ope_s[4][512];
    int row0 = blockIdx.x * 4;
    int t = threadIdx.x;
    for (int idx = t; idx < 8192; idx += 512) {
        int r = idx >> 11, rest = idx & 2047, h = rest >> 8, c = rest & 255;
        int row = row0 + r, b = row >> 4, e = row & 15;
        float s = 0.f;
        #pragma unroll
        for (int ks = 0; ks < 16; ks++)
            s += g_PAP[(size_t)((ks * 8 + b) * 128 + h * 16 + e) * 256 + c];
        pool[idx] = s * wp[c];
    }
    for (int idx = t; idx < 2048; idx += 512) {
        int r = idx >> 9, j = idx & 511;
        int row = row0 + r, b = row >> 4, e = row & 15;
        int h = j >> 6, d = j & 63;
        float s = 0.f;
        #pragma unroll
        for (int ks = 0; ks < 8; ks++)
            s += g_OPEP[(size_t)((ks * 8 + h) * 128 + b * 16 + e) * 64 + d];
        ope_s[r][j] = s;
    }
    __syncthreads();
    int tj = t & 127, tk = t >> 7;
    int h = tj >> 4;
    float4 acc[4];
    #pragma unroll
    for (int r = 0; r < 4; r++) acc[r] = make_float4(0.f, 0.f, 0.f, 0.f);
    #pragma unroll 4
    for (int c = tk * 64; c < tk * 64 + 64; c++) {
        float4 w4 = *(const float4*)&wkv[(size_t)c * 1024 + 512 + tj * 4];
        #pragma unroll
        for (int r = 0; r < 4; r++) {
            float p = pool[r * 2048 + h * 256 + c];
            acc[r].x += p * w4.x; acc[r].y += p * w4.y;
            acc[r].z += p * w4.z; acc[r].w += p * w4.w;
        }
    }
    __syncthreads();
    #pragma unroll
    for (int r = 0; r < 4; r++) *(float4*)&pool[(tk * 4 + r) * 512 + tj * 4] = acc[r];
    __syncthreads();
    {
        int r = t >> 7, j0 = (t & 127) * 4;
        float4 s = make_float4(0.f, 0.f, 0.f, 0.f);
        #pragma unroll
        for (int k2 = 0; k2 < 4; k2++) {
            float4 p = *(const float4*)&pool[(k2 * 4 + r) * 512 + j0];
            s.x += p.x; s.y += p.y; s.z += p.z; s.w += p.w;
        }
        float4 op = *(const float4*)&ope_s[r][j0];
        s.x += op.x; s.y += op.y; s.z += op.z; s.w += op.w;
        *(float4*)&g_ATT0[(row0 + r) * 512 + j0] = s;
    }
}

// ---------------- K10: proj + residual ---------------------------------------------
__global__ void __launch_bounds__(256) k_proj(const float* __restrict__ wproj,
                                              const float* __restrict__ bproj) {
    __shared__ float x_s[8][512];
    __shared__ float part[8][8][128];
    int row0 = blockIdx.x * 8, jb = blockIdx.y * 128, t = threadIdx.x;
    for (int idx = t; idx < 4096; idx += 256)
        x_s[idx >> 9][idx & 511] = g_ATT0[(row0 + (idx >> 9)) * 512 + (idx & 511)];
    __syncthreads();
    int tk = t >> 5, tj = t & 31, j = jb + tj * 4;
    float4 acc[8];
    #pragma unroll
    for (int r = 0; r < 8; r++) acc[r] = make_float4(0.f, 0.f, 0.f, 0.f);
    #pragma unroll 8
    for (int c = tk * 64; c < tk * 64 + 64; c++) {
        float4 w4 = *(const float4*)&wproj[(size_t)c * 512 + j];
        #pragma unroll
        for (int r = 0; r < 8; r++) {
            float x = x_s[r][c];
            acc[r].x += x * w4.x; acc[r].y += x * w4.y;
            acc[r].z += x * w4.z; acc[r].w += x * w4.w;
        }
    }
    #pragma unroll
    for (int r = 0; r < 8; r++) *(float4*)&part[tk][r][tj * 4] = acc[r];
    __syncthreads();
    {
        int r = t >> 5, cq = t & 31, j2 = jb + cq * 4;
        float4 s = make_float4(0.f, 0.f, 0.f, 0.f);
        #pragma unroll
        for (int k2 = 0; k2 < 8; k2++) {
            float4 p = *(const float4*)&part[k2][r][cq * 4];
            s.x += p.x; s.y += p.y; s.z += p.z; s.w += p.w;
        }
        float4 bp = *(const float4*)&bproj[j2];
        float4 mn = *(const float4*)&g_MOLN[(row0 + r) * 512 + j2];
        s.x += bp.x + mn.x; s.y += bp.y + mn.y;
        s.z += bp.z + mn.z; s.w += bp.w + mn.w;
        *(float4*)&g_ATT[(row0 + r) * 512 + j2] = s;
    }
}

// ---------------- K11: ffn1 (fused rmsnorm) + gelu ----------------------------------
__global__ void __launch_bounds__(256) k_ffn1(const float* __restrict__ nw,
                                              const float* __restrict__ w1,
                                              const float* __restrict__ b1) {
    __shared__ float x_s[8][512];
    __shared__ float part[8][8][128];
    int row0 = blockIdx.x * 8, jb = blockIdx.y * 128, t = threadIdx.x;
    int w = t >> 5, lane = t & 31;
    {
        float vals[16]; float ss = 0.f;
        #pragma unroll
        for (int i = 0; i < 16; i++) {
            float v = g_ATT[(row0 + w) * 512 + lane + i * 32];
            vals[i] = v; ss += v * v;
        }
        #pragma unroll
        for (int o = 16; o; o >>= 1) ss += __shfl_xor_sync(0xffffffffu, ss, o);
        float rv = rsqrtf(ss * (1.0f / 512.0f) + EPSV);
        #pragma unroll
        for (int i = 0; i < 16; i++) {
            int m = lane + i * 32;
            x_s[w][m] = vals[i] * rv * nw[m];
        }
    }
    __syncthreads();
    int tk = t >> 5, tj = t & 31, j = jb + tj * 4;
    float4 acc[8];
    #pragma unroll
    for (int r = 0; r < 8; r++) acc[r] = make_float4(0.f, 0.f, 0.f, 0.f);
    #pragma unroll 8
    for (int c = tk * 64; c < tk * 64 + 64; c++) {
        float4 w4 = *(const float4*)&w1[(size_t)c * 2048 + j];
        #pragma unroll
        for (int r = 0; r < 8; r++) {
            float x = x_s[r][c];
            acc[r].x += x * w4.x; acc[r].y += x * w4.y;
            acc[r].z += x * w4.z; acc[r].w += x * w4.w;
        }
    }
    #pragma unroll
    for (int r = 0; r < 8; r++) *(float4*)&part[tk][r][tj * 4] = acc[r];
    __syncthreads();
    {
        int r = t >> 5, cq = t & 31, j2 = jb + cq * 4;
        float4 s = make_float4(0.f, 0.f, 0.f, 0.f);
        #pragma unroll
        for (int k2 = 0; k2 < 8; k2++) {
            float4 p = *(const float4*)&part[k2][r][cq * 4];
            s.x += p.x; s.y += p.y; s.z += p.z; s.w += p.w;
        }
        float4 bb = *(const float4*)&b1[j2];
        float4 o;
        o.x = geluf(s.x + bb.x); o.y = geluf(s.y + bb.y);
        o.z = geluf(s.z + bb.z); o.w = geluf(s.w + bb.w);
        *(float4*)&g_H1[(size_t)(row0 + r) * 2048 + j2] = o;
    }
}

// ---------------- K12: ffn2 + residual ----------------------------------------------
__global__ void __launch_bounds__(512) k_ffn2(const float* __restrict__ w2,
                                              const float* __restrict__ b2,
                                              float* __restrict__ out) {
    __shared__ float pool[8192];
    int row0 = blockIdx.x * 4, jb = blockIdx.y * 128, t = threadIdx.x;
    for (int idx = t; idx < 8192; idx += 512)
        pool[idx] = g_H1[(size_t)(row0 + (idx >> 11)) * 2048 + (idx & 2047)];
    __syncthreads();
    int tk = t >> 5, tj = t & 31, j = jb + tj * 4;
    float4 acc[4];
    #pragma unroll
    for (int r = 0; r < 4; r++) acc[r] = make_float4(0.f, 0.f, 0.f, 0.f);
    #pragma unroll 8
    for (int c = tk * 128; c < tk * 128 + 128; c++) {
        float4 w4 = *(const float4*)&w2[(size_t)c * 512 + j];
        #pragma unroll
        for (int r = 0; r < 4; r++) {
            float x = pool[r * 2048 + c];
            acc[r].x += x * w4.x; acc[r].y += x * w4.y;
            acc[r].z += x * w4.z; acc[r].w += x * w4.w;
        }
    }
    __syncthreads();
    #pragma unroll
    for (int r = 0; r < 4; r++) *(float4*)&pool[tk * 512 + r * 128 + tj * 4] = acc[r];
    __syncthreads();
    {
        int r = t >> 7, cq = t & 127;
        float s = 0.f;
        #pragma unroll
        for (int k2 = 0; k2 < 16; k2++) s += pool[k2 * 512 + r * 128 + cq];
        int j2 = jb + cq;
        out[(row0 + r) * 512 + j2] = s + b2[j2] + g_ATT[(row0 + r) * 512 + j2];
    }
}

// ---------------- launch -------------------------------------------------------------
extern "C" void kernel_launch(void* const* d_in, const int* in_sizes, int n_in,
                              void* d_out, int out_size) {
    const float* patch   = (const float*)d_in[0];
    const float* mol     = (const float*)d_in[1];
    const float* pe_w1   = (const float*)d_in[2];
    const float* pe_b1   = (const float*)d_in[3];
    const float* pe_w2   = (const float*)d_in[4];
    const float* pe_b2   = (const float*)d_in[5];
    const float* wq      = (const float*)d_in[6];
    const float* bq      = (const float*)d_in[7];
    const float* wkv     = (const float*)d_in[8];
    const float* bkv     = (const float*)d_in[9];
    const float* wproj   = (const float*)d_in[10];
    const float* bproj   = (const float*)d_in[11];
    const float* nmolw   = (const float*)d_in[12];
    const float* npatchw = (const float*)d_in[13];
    const float* ffn_w1  = (const float*)d_in[14];
    const float* ffn_b1  = (const float*)d_in[15];
    const float* ffn_w2  = (const float*)d_in[16];
    const float* ffn_b2  = (const float*)d_in[17];
    const float* ffn_nw  = (const float*)d_in[18];
    float* out = (float*)d_out;
    (void)in_sizes; (void)n_in; (void)out_size;

    k_peg_tc   <<<dim3(32, 4), 256>>>(pe_w1, pe_b1, pe_w2);
    k_molq     <<<dim3(16, 4), 256>>>(mol, nmolw, wq, bq);
    k_tq2      <<<dim3(8, 2), 256>>>(wkv, npatchw);
    k_qpe_tc   <<<dim3(32, 8), 256>>>();
    k_scores_tc<<<dim3(32, 8), 256>>>(patch);
    k_softmax  <<<BB * 128, 512>>>();
    k_pa_tc    <<<dim3(16, 8), 512>>>(patch);
    k_ppe_tc   <<<dim3(8, 8), 256>>>(bkv, pe_b2);
    k_out      <<<32, 512>>>(wkv, npatchw);
    k_proj     <<<dim3(16, 4), 256>>>(wproj, bproj);
    k_ffn1     <<<dim3(16, 16), 256>>>(ffn_nw, ffn_w1, ffn_b1);
    k_ffn2     <<<dim3(32, 4), 512>>>(ffn_w2, ffn_b2, out);
}

// round 16
// speedup vs baseline: 1.0255x; 1.0011x over previous
#include <cuda_runtime.h>
#include <mma.h>
#include <math.h>

using namespace nvcuda;

#define BB 8
#define CC 256
#define NN 4096
#define MM 512
#define EE 16
#define NH 8
#define FFNH 2048
#define EPSV 1.1920929e-07f

// ------------- scratch (__device__ globals; no allocation allowed) ---------------
__device__ float g_PE  [NN * MM];             // pos_enc G@W2 (NO bias)
__device__ float g_RINV[BB * NN];             // patch rmsnorm rsqrt (written by k_scores_tc)
__device__ float g_Q   [128 * 512];           // q rows=(b,e) (includes bq)
__device__ float g_MOLN[128 * 512];           // normalized mol (residual)
__device__ float g_TQ  [BB * 128 * 256];      // tq' rows=(b, h*16+e), wp & 0.125 folded
__device__ float g_S   [(size_t)BB * 128 * NN];       // raw scores (never normalized in place)
__device__ float g_SMX [1024 * 2];            // per-row (max, 1/sum) for softmax
__device__ float g_PAP [(size_t)16 * BB * 128 * 256]; // pa partials   16.8 MB
__device__ float g_OPEP[8 * 8 * 128 * 64];    // p@(pe+bv+b2) partials
__device__ float g_ATT0[128 * 512];           // attention out (pre-proj)
__device__ float g_ATT [128 * 512];           // attended (post residual)
__device__ float g_H1  [128 * 2048];          // ffn hidden

__device__ __forceinline__ float geluf(float x) {
    return 0.5f * x * (1.0f + erff(x * 0.70710678118654752440f));
}

template <int NWARPS, bool DOMAX>
__device__ __forceinline__ float blk_red(float v, float* red) {
    #pragma unroll
    for (int o = 16; o; o >>= 1) {
        float t = __shfl_xor_sync(0xffffffffu, v, o);
        v = DOMAX ? fmaxf(v, t) : v + t;
    }
    if ((threadIdx.x & 31) == 0) red[threadIdx.x >> 5] = v;
    __syncthreads();
    if (threadIdx.x < 32) {
        float r = (threadIdx.x < NWARPS) ? red[threadIdx.x] : (DOMAX ? -1e30f : 0.0f);
        #pragma unroll
        for (int o = NWARPS >> 1; o; o >>= 1) {
            float t = __shfl_xor_sync(0xffffffffu, r, o);
            r = DOMAX ? fmaxf(r, t) : r + t;
        }
        if (threadIdx.x == 0) red[0] = r;
    }
    __syncthreads();
    float s = red[0];
    __syncthreads();
    return s;
}

// ---------------- K1: PE = gelu(coords@W1+b1) @ W2 (tf32 TC, gelu fused) -----------
__global__ void __launch_bounds__(256) k_peg_tc(const float* __restrict__ w1,
                                                const float* __restrict__ b1,
                                                const float* __restrict__ w2) {
    __shared__ __align__(16) float As[128][36];
    __shared__ __align__(16) float Bs[32][132];
    int m0 = blockIdx.x * 128, j0 = blockIdx.y * 128, t = threadIdx.x;
    int w = t >> 5, wm = w >> 2, wn = w & 3;
    wmma::fragment<wmma::accumulator, 16, 16, 8, float> c[4][2];
    #pragma unroll
    for (int mi = 0; mi < 4; mi++)
        #pragma unroll
        for (int ni = 0; ni < 2; ni++) wmma::fill_fragment(c[mi][ni], 0.0f);
    for (int c0 = 0; c0 < 256; c0 += 32) {
        #pragma unroll
        for (int r = 0; r < 4; r++) {
            int i = t + 256 * r, row = i >> 3, kq = i & 7;
            int n = m0 + row;
            float cd = (float)(n >> 8)        * 0.0625f;
            float chc = (float)((n >> 4) & 15) * 0.0625f;
            float cw = (float)(n & 15)        * 0.0625f;
            int k = c0 + kq * 4;
            float4 wd = *(const float4*)&w1[k];
            float4 wh = *(const float4*)&w1[256 + k];
            float4 ww = *(const float4*)&w1[512 + k];
            float4 bb = *(const float4*)&b1[k];
            As[row][kq * 4 + 0] = wmma::__float_to_tf32(geluf(cd * wd.x + chc * wh.x + cw * ww.x + bb.x));
            As[row][kq * 4 + 1] = wmma::__float_to_tf32(geluf(cd * wd.y + chc * wh.y + cw * ww.y + bb.y));
            As[row][kq * 4 + 2] = wmma::__float_to_tf32(geluf(cd * wd.z + chc * wh.z + cw * ww.z + bb.z));
            As[row][kq * 4 + 3] = wmma::__float_to_tf32(geluf(cd * wd.w + chc * wh.w + cw * ww.w + bb.w));
        }
        #pragma unroll
        for (int r = 0; r < 4; r++) {
            int i = t + 256 * r, kk = i >> 5, nq = i & 31;
            float4 v = *(const float4*)&w2[(size_t)(c0 + kk) * 512 + j0 + nq * 4];
            Bs[kk][nq * 4 + 0] = wmma::__float_to_tf32(v.x);
            Bs[kk][nq * 4 + 1] = wmma::__float_to_tf32(v.y);
            Bs[kk][nq * 4 + 2] = wmma::__float_to_tf32(v.z);
            Bs[kk][nq * 4 + 3] = wmma::__float_to_tf32(v.w);
        }
        __syncthreads();
        #pragma unroll
        for (int kf = 0; kf < 4; kf++) {
            wmma::fragment<wmma::matrix_a, 16, 16, 8, wmma::precision::tf32, wmma::row_major> af[4];
            wmma::fragment<wmma::matrix_b, 16, 16, 8, wmma::precision::tf32, wmma::row_major> bf[2];
            #pragma unroll
            for (int mi = 0; mi < 4; mi++)
                wmma::load_matrix_sync(af[mi], &As[wm * 64 + mi * 16][kf * 8], 36);
            #pragma unroll
            for (int ni = 0; ni < 2; ni++)
                wmma::load_matrix_sync(bf[ni], &Bs[kf * 8][wn * 32 + ni * 16], 132);
            #pragma unroll
            for (int mi = 0; mi < 4; mi++)
                #pragma unroll
                for (int ni = 0; ni < 2; ni++)
                    wmma::mma_sync(c[mi][ni], af[mi], bf[ni], c[mi][ni]);
        }
        __syncthreads();
    }
    #pragma unroll
    for (int mi = 0; mi < 4; mi++)
        #pragma unroll
        for (int ni = 0; ni < 2; ni++)
            wmma::store_matrix_sync(&g_PE[(size_t)(m0 + wm * 64 + mi * 16) * 512 + j0 + wn * 32 + ni * 16],
                                    c[mi][ni], 512, wmma::mem_row_major);
}

// ---------------- K2: mol rmsnorm + Q projection (+bq) -----------------------------
__global__ void __launch_bounds__(256) k_molq(const float* __restrict__ mol,
                                              const float* __restrict__ wmol,
                                              const float* __restrict__ wq,
                                              const float* __restrict__ bq) {
    __shared__ float x_s[8][512];
    __shared__ float part[8][8][128];
    int row0 = blockIdx.x * 8, jb = blockIdx.y * 128;
    int t = threadIdx.x;
    int w = t >> 5, lane = t & 31;
    float vals[16]; float ss = 0.0f;
    #pragma unroll
    for (int i = 0; i < 16; i++) {
        float v = mol[(row0 + w) * 512 + lane + i * 32];
        vals[i] = v; ss += v * v;
    }
    #pragma unroll
    for (int o = 16; o; o >>= 1) ss += __shfl_xor_sync(0xffffffffu, ss, o);
    float rv = rsqrtf(ss * (1.0f / 512.0f) + EPSV);
    #pragma unroll
    for (int i = 0; i < 16; i++) {
        int m = lane + i * 32;
        float xn = vals[i] * rv * wmol[m];
        x_s[w][m] = xn;
        if (blockIdx.y == 0) g_MOLN[(row0 + w) * 512 + m] = xn;
    }
    __syncthreads();
    int tk = w, tj = lane, j = jb + tj * 4;
    float4 acc[8];
    #pragma unroll
    for (int r = 0; r < 8; r++) acc[r] = make_float4(0.f, 0.f, 0.f, 0.f);
    #pragma unroll 8
    for (int c = tk * 64; c < tk * 64 + 64; c++) {
        float4 w4 = *(const float4*)&wq[(size_t)c * 512 + j];
        #pragma unroll
        for (int r = 0; r < 8; r++) {
            float x = x_s[r][c];
            acc[r].x += x * w4.x; acc[r].y += x * w4.y;
            acc[r].z += x * w4.z; acc[r].w += x * w4.w;
        }
    }
    #pragma unroll
    for (int r = 0; r < 8; r++) *(float4*)&part[tk][r][tj * 4] = acc[r];
    __syncthreads();
    {
        int r = t >> 5, cq = t & 31, j2 = jb + cq * 4;
        float4 s = make_float4(0.f, 0.f, 0.f, 0.f);
        #pragma unroll
        for (int k2 = 0; k2 < 8; k2++) {
            float4 p = *(const float4*)&part[k2][r][cq * 4];
            s.x += p.x; s.y += p.y; s.z += p.z; s.w += p.w;
        }
        float4 bv = *(const float4*)&bq[j2];
        s.x += bv.x; s.y += bv.y; s.z += bv.z; s.w += bv.w;
        *(float4*)&g_Q[(row0 + r) * 512 + j2] = s;
    }
}

// ---------------- K3: tq' = 0.125*wp[c]*(q_h . Wk_h[c,:]) --------------------------
__global__ void __launch_bounds__(256) k_tq2(const float* __restrict__ wkv,
                                             const float* __restrict__ wp) {
    __shared__ float As[16][128];
    __shared__ float Bs[16][128];
    int h = blockIdx.x, c0b = blockIdx.y * 128, t = threadIdx.x;
    int tr = t >> 4, tc = t & 15;
    float acc[8][8];
    #pragma unroll
    for (int i = 0; i < 8; i++)
        #pragma unroll
        for (int j = 0; j < 8; j++) acc[i][j] = 0.f;
    for (int k0 = 0; k0 < 64; k0 += 16) {
        {
            int r = t >> 1, k8 = (t & 1) * 8;
            const float* src = &g_Q[r * 512 + h * 64 + k0 + k8];
            float4 a0 = *(const float4*)&src[0];
            float4 a1 = *(const float4*)&src[4];
            As[k8 + 0][r] = a0.x; As[k8 + 1][r] = a0.y; As[k8 + 2][r] = a0.z; As[k8 + 3][r] = a0.w;
            As[k8 + 4][r] = a1.x; As[k8 + 5][r] = a1.y; As[k8 + 6][r] = a1.z; As[k8 + 7][r] = a1.w;
        }
        {
            int c = t >> 1, k8 = (t & 1) * 8;
            const float* src = &wkv[(size_t)(c0b + c) * 1024 + h * 64 + k0 + k8];
            float4 v0 = *(const float4*)&src[0];
            float4 v1 = *(const float4*)&src[4];
            Bs[k8 + 0][c] = v0.x; Bs[k8 + 1][c] = v0.y; Bs[k8 + 2][c] = v0.z; Bs[k8 + 3][c] = v0.w;
            Bs[k8 + 4][c] = v1.x; Bs[k8 + 5][c] = v1.y; Bs[k8 + 6][c] = v1.z; Bs[k8 + 7][c] = v1.w;
        }
        __syncthreads();
        #pragma unroll
        for (int kk = 0; kk < 16; kk++) {
            float4 a0 = *(const float4*)&As[kk][tr * 8];
            float4 a1 = *(const float4*)&As[kk][tr * 8 + 4];
            float4 b0 = *(const float4*)&Bs[kk][tc * 8];
            float4 b1 = *(const float4*)&Bs[kk][tc * 8 + 4];
            float a[8] = {a0.x, a0.y, a0.z, a0.w, a1.x, a1.y, a1.z, a1.w};
            float bb[8] = {b0.x, b0.y, b0.z, b0.w, b1.x, b1.y, b1.z, b1.w};
            #pragma unroll
            for (int i = 0; i < 8; i++)
                #pragma unroll
                for (int j = 0; j < 8; j++) acc[i][j] += a[i] * bb[j];
        }
        __syncthreads();
    }
    float4 wp0 = *(const float4*)&wp[c0b + tc * 8];
    float4 wp1 = *(const float4*)&wp[c0b + tc * 8 + 4];
    float wpv[8] = {wp0.x, wp0.y, wp0.z, wp0.w, wp1.x, wp1.y, wp1.z, wp1.w};
    #pragma unroll
    for (int i = 0; i < 8; i++) {
        int r = tr * 8 + i, b = r >> 4, e = r & 15;
        float* dst = &g_TQ[(size_t)(b * 128 + h * 16 + e) * 256 + c0b + tc * 8];
        #pragma unroll
        for (int j = 0; j < 8; j++) dst[j] = acc[i][j] * wpv[j] * 0.125f;
    }
}

// ---------------- K4: S = (0.125*q_h) @ PE_h^T  (tf32 TC, K=64, col-major B) -------
__global__ void __launch_bounds__(256) k_qpe_tc() {
    __shared__ __align__(16) float As[128][36];
    __shared__ __align__(16) float Bs[128][36];
    int n0 = blockIdx.x * 128, h = blockIdx.y, t = threadIdx.x;
    int w = t >> 5, wm = w >> 2, wn = w & 3;
    wmma::fragment<wmma::accumulator, 16, 16, 8, float> c[4][2];
    #pragma unroll
    for (int mi = 0; mi < 4; mi++)
        #pragma unroll
        for (int ni = 0; ni < 2; ni++) wmma::fill_fragment(c[mi][ni], 0.0f);
    for (int c0 = 0; c0 < 64; c0 += 32) {
        #pragma unroll
        for (int r = 0; r < 4; r++) {
            int i = t + 256 * r, row = i >> 3, kq = i & 7;
            float4 v = *(const float4*)&g_Q[row * 512 + h * 64 + c0 + kq * 4];
            As[row][kq * 4 + 0] = wmma::__float_to_tf32(0.125f * v.x);
            As[row][kq * 4 + 1] = wmma::__float_to_tf32(0.125f * v.y);
            As[row][kq * 4 + 2] = wmma::__float_to_tf32(0.125f * v.z);
            As[row][kq * 4 + 3] = wmma::__float_to_tf32(0.125f * v.w);
        }
        #pragma unroll
        for (int r = 0; r < 4; r++) {
            int i = t + 256 * r, row = i >> 3, kq = i & 7;
            float4 v = *(const float4*)&g_PE[(size_t)(n0 + row) * 512 + h * 64 + c0 + kq * 4];
            Bs[row][kq * 4 + 0] = wmma::__float_to_tf32(v.x);
            Bs[row][kq * 4 + 1] = wmma::__float_to_tf32(v.y);
            Bs[row][kq * 4 + 2] = wmma::__float_to_tf32(v.z);
            Bs[row][kq * 4 + 3] = wmma::__float_to_tf32(v.w);
        }
        __syncthreads();
        #pragma unroll
        for (int kf = 0; kf < 4; kf++) {
            wmma::fragment<wmma::matrix_a, 16, 16, 8, wmma::precision::tf32, wmma::row_major> af[4];
            wmma::fragment<wmma::matrix_b, 16, 16, 8, wmma::precision::tf32, wmma::col_major> bf[2];
            #pragma unroll
            for (int mi = 0; mi < 4; mi++)
                wmma::load_matrix_sync(af[mi], &As[wm * 64 + mi * 16][kf * 8], 36);
            #pragma unroll
            for (int ni = 0; ni < 2; ni++)
                wmma::load_matrix_sync(bf[ni], &Bs[wn * 32 + ni * 16][kf * 8], 36);
            #pragma unroll
            for (int mi = 0; mi < 4; mi++)
                #pragma unroll
                for (int ni = 0; ni < 2; ni++)
                    wmma::mma_sync(c[mi][ni], af[mi], bf[ni], c[mi][ni]);
        }
        __syncthreads();
    }
    #pragma unroll
    for (int mi = 0; mi < 4; mi++) {
        int r0 = wm * 64 + mi * 16;
        int b = r0 >> 4;
        float* dst = &g_S[(size_t)((b * 8 + h) * 16) * 4096 + n0 + wn * 32];
        #pragma unroll
        for (int ni = 0; ni < 2; ni++)
            wmma::store_matrix_sync(dst + ni * 16, c[mi][ni], 4096, wmma::mem_row_major);
    }
}

// ---------------- K5: scores (tf32 TC, rinv fused): S += tq' @ (X*rinv) ------------
__global__ void __launch_bounds__(256) k_scores_tc(const float* __restrict__ X) {
    __shared__ __align__(16) float As[128][36];
    __shared__ __align__(16) float Bs[32][132];
    __shared__ __align__(16) float rs[128];
    __shared__ float ss2[256];
    int n0 = blockIdx.x * 128, b = blockIdx.y, t = threadIdx.x;
    int w = t >> 5, wm = w >> 2, wn = w & 3;
    const float* Xb = X + (size_t)b * CC * NN;
    const float* TQ = g_TQ + (size_t)b * 128 * 256;
    float* Sb = g_S + (size_t)b * 128 * 4096;
    {
        int tn = t & 127, chh = t >> 7;
        const float* xp = Xb + (size_t)(chh * 128) * 4096 + n0 + tn;
        float s0 = 0.f, s1 = 0.f, s2 = 0.f, s3 = 0.f;
        #pragma unroll 4
        for (int c = 0; c < 128; c += 4) {
            float v0 = xp[(size_t)(c + 0) * 4096];
            float v1 = xp[(size_t)(c + 1) * 4096];
            float v2 = xp[(size_t)(c + 2) * 4096];
            float v3 = xp[(size_t)(c + 3) * 4096];
            s0 += v0 * v0; s1 += v1 * v1; s2 += v2 * v2; s3 += v3 * v3;
        }
        ss2[t] = (s0 + s1) + (s2 + s3);
    }
    __syncthreads();
    if (t < 128) {
        float rv = rsqrtf((ss2[t] + ss2[t + 128]) * (1.0f / 256.0f) + EPSV);
        rs[t] = rv;
        g_RINV[b * 4096 + n0 + t] = rv;
    }
    __syncthreads();
    wmma::fragment<wmma::accumulator, 16, 16, 8, float> c[4][2];
    #pragma unroll
    for (int mi = 0; mi < 4; mi++)
        #pragma unroll
        for (int ni = 0; ni < 2; ni++)
            wmma::load_matrix_sync(c[mi][ni],
                &Sb[(size_t)(wm * 64 + mi * 16) * 4096 + n0 + wn * 32 + ni * 16],
                4096, wmma::mem_row_major);
    for (int c0 = 0; c0 < 256; c0 += 32) {
        #pragma unroll
        for (int r = 0; r < 4; r++) {
            int i = t + 256 * r, row = i >> 3, kq = i & 7;
            float4 v = *(const float4*)&TQ[(size_t)row * 256 + c0 + kq * 4];
            As[row][kq * 4 + 0] = wmma::__float_to_tf32(v.x);
            As[row][kq * 4 + 1] = wmma::__float_to_tf32(v.y);
            As[row][kq * 4 + 2] = wmma::__float_to_tf32(v.z);
            As[row][kq * 4 + 3] = wmma::__float_to_tf32(v.w);
        }
        #pragma unroll
        for (int r = 0; r < 4; r++) {
            int i = t + 256 * r, kk = i >> 5, nq = i & 31;
            float4 v = *(const float4*)&Xb[(size_t)(c0 + kk) * 4096 + n0 + nq * 4];
            Bs[kk][nq * 4 + 0] = wmma::__float_to_tf32(v.x * rs[nq * 4 + 0]);
            Bs[kk][nq * 4 + 1] = wmma::__float_to_tf32(v.y * rs[nq * 4 + 1]);
            Bs[kk][nq * 4 + 2] = wmma::__float_to_tf32(v.z * rs[nq * 4 + 2]);
            Bs[kk][nq * 4 + 3] = wmma::__float_to_tf32(v.w * rs[nq * 4 + 3]);
        }
        __syncthreads();
        #pragma unroll
        for (int kf = 0; kf < 4; kf++) {
            wmma::fragment<wmma::matrix_a, 16, 16, 8, wmma::precision::tf32, wmma::row_major> af[4];
            wmma::fragment<wmma::matrix_b, 16, 16, 8, wmma::precision::tf32, wmma::row_major> bf[2];
            #pragma unroll
            for (int mi = 0; mi < 4; mi++)
                wmma::load_matrix_sync(af[mi], &As[wm * 64 + mi * 16][kf * 8], 36);
            #pragma unroll
            for (int ni = 0; ni < 2; ni++)
                wmma::load_matrix_sync(bf[ni], &Bs[kf * 8][wn * 32 + ni * 16], 132);
            #pragma unroll
            for (int mi = 0; mi < 4; mi++)
                #pragma unroll
                for (int ni = 0; ni < 2; ni++)
                    wmma::mma_sync(c[mi][ni], af[mi], bf[ni], c[mi][ni]);
        }
        __syncthreads();
    }
    #pragma unroll
    for (int mi = 0; mi < 4; mi++)
        #pragma unroll
        for (int ni = 0; ni < 2; ni++)
            wmma::store_matrix_sync(&Sb[(size_t)(wm * 64 + mi * 16) * 4096 + n0 + wn * 32 + ni * 16],
                                    c[mi][ni], 4096, wmma::mem_row_major);
}

// ---------------- K6: msum — per-row softmax (max, 1/sum); S left raw --------------
__global__ void k_msum() {
    __shared__ float red[32];
    int row = blockIdx.x;   // 0..1023
    const float* s = g_S + (size_t)row * NN;
    int t = threadIdx.x;    // 512
    float loc[8];
    float m = -1e30f;
    #pragma unroll
    for (int i = 0; i < 8; i++) { loc[i] = s[t + i * 512]; m = fmaxf(m, loc[i]); }
    m = blk_red<16, true>(m, red);
    float sum = 0.0f;
    #pragma unroll
    for (int i = 0; i < 8; i++) sum += __expf(loc[i] - m);
    sum = blk_red<16, false>(sum, red);
    if (t == 0) {
        g_SMX[row * 2 + 0] = m;
        g_SMX[row * 2 + 1] = 1.0f / sum;
    }
}

// ---------------- K7: pa partials (tf32 TC): softmax applied in staging ------------
// A = __expf(s - m)*inv * rinv  — identical fp ops to the old stored-p path.
__global__ void __launch_bounds__(512) k_pa_tc(const float* __restrict__ X) {
    __shared__ __align__(16) float As[128][20];
    __shared__ __align__(16) float Bs[256][20];
    int ks = blockIdx.x, b = blockIdx.y, t = threadIdx.x;
    int nbase = ks * 256;
    int w = t >> 5, wm = w >> 3, wn = w & 7;
    const float* Xb = X + (size_t)b * CC * NN;
    // per-thread row constants (row is loop-invariant for the A-staging thread)
    int arow = t >> 2;
    float smx_m   = g_SMX[(b * 128 + arow) * 2 + 0];
    float smx_inv = g_SMX[(b * 128 + arow) * 2 + 1];
    wmma::fragment<wmma::accumulator, 16, 16, 8, float> c[4][2];
    #pragma unroll
    for (int mi = 0; mi < 4; mi++)
        #pragma unroll
        for (int ni = 0; ni < 2; ni++) wmma::fill_fragment(c[mi][ni], 0.0f);
    for (int k0 = 0; k0 < 256; k0 += 16) {
        {
            int kq = t & 3;
            int n = nbase + k0 + kq * 4;
            float4 p  = *(const float4*)&g_S[(size_t)(b * 128 + arow) * 4096 + n];
            float4 rv = *(const float4*)&g_RINV[b * 4096 + n];
            As[arow][kq * 4 + 0] = wmma::__float_to_tf32(__expf(p.x - smx_m) * smx_inv * rv.x);
            As[arow][kq * 4 + 1] = wmma::__float_to_tf32(__expf(p.y - smx_m) * smx_inv * rv.y);
            As[arow][kq * 4 + 2] = wmma::__float_to_tf32(__expf(p.z - smx_m) * smx_inv * rv.z);
            As[arow][kq * 4 + 3] = wmma::__float_to_tf32(__expf(p.w - smx_m) * smx_inv * rv.w);
        }
        #pragma unroll
        for (int r = 0; r < 2; r++) {
            int i = t + 512 * r, cc = i >> 2, kq = i & 3;
            float4 v = *(const float4*)&Xb[(size_t)cc * 4096 + nbase + k0 + kq * 4];
            Bs[cc][kq * 4 + 0] = wmma::__float_to_tf32(v.x);
            Bs[cc][kq * 4 + 1] = wmma::__float_to_tf32(v.y);
            Bs[cc][kq * 4 + 2] = wmma::__float_to_tf32(v.z);
            Bs[cc][kq * 4 + 3] = wmma::__float_to_tf32(v.w);
        }
        __syncthreads();
        #pragma unroll
        for (int kf = 0; kf < 2; kf++) {
            wmma::fragment<wmma::matrix_a, 16, 16, 8, wmma::precision::tf32, wmma::row_major> af[4];
            wmma::fragment<wmma::matrix_b, 16, 16, 8, wmma::precision::tf32, wmma::col_major> bf[2];
            #pragma unroll
            for (int mi = 0; mi < 4; mi++)
                wmma::load_matrix_sync(af[mi], &As[wm * 64 + mi * 16][kf * 8], 20);
            #pragma unroll
            for (int ni = 0; ni < 2; ni++)
                wmma::load_matrix_sync(bf[ni], &Bs[wn * 32 + ni * 16][kf * 8], 20);
            #pragma unroll
            for (int mi = 0; mi < 4; mi++)
                #pragma unroll
                for (int ni = 0; ni < 2; ni++)
                    wmma::mma_sync(c[mi][ni], af[mi], bf[ni], c[mi][ni]);
        }
        __syncthreads();
    }
    #pragma unroll
    for (int mi = 0; mi < 4; mi++)
        #pragma unroll
        for (int ni = 0; ni < 2; ni++)
            wmma::store_matrix_sync(
                &g_PAP[(size_t)((ks * 8 + b) * 128 + wm * 64 + mi * 16) * 256 + wn * 32 + ni * 16],
                c[mi][ni], 256, wmma::mem_row_major);
}

// ---------------- K8: ope partials (tf32 TC): softmax in staging; B = PE+bv+b2 -----
__global__ void __launch_bounds__(256) k_ppe_tc(const float* __restrict__ bkv,
                                                const float* __restrict__ peb2) {
    __shared__ __align__(16) float As[128][36];
    __shared__ __align__(16) float Bs[32][68];
    __shared__ float bias_s[64];
    __shared__ float m_s[128];
    __shared__ float i_s[128];
    int h = blockIdx.x, ks = blockIdx.y, t = threadIdx.x;
    int nb = ks * 512;
    int w = t >> 5, wm = w >> 1, wn = w & 1;
    if (t < 16) {
        float4 bv4 = *(const float4*)&bkv[512 + h * 64 + t * 4];
        float4 b24 = *(const float4*)&peb2[h * 64 + t * 4];
        bias_s[t * 4 + 0] = bv4.x + b24.x;
        bias_s[t * 4 + 1] = bv4.y + b24.y;
        bias_s[t * 4 + 2] = bv4.z + b24.z;
        bias_s[t * 4 + 3] = bv4.w + b24.w;
    }
    if (t < 128) {
        int b = t >> 4, e = t & 15;
        int sr = (b * 8 + h) * 16 + e;
        m_s[t] = g_SMX[sr * 2 + 0];
        i_s[t] = g_SMX[sr * 2 + 1];
    }
    __syncthreads();
    wmma::fragment<wmma::accumulator, 16, 16, 8, float> c[2][2];
    #pragma unroll
    for (int mi = 0; mi < 2; mi++)
        #pragma unroll
        for (int ni = 0; ni < 2; ni++) wmma::fill_fragment(c[mi][ni], 0.0f);
    for (int k0 = 0; k0 < 512; k0 += 32) {
        #pragma unroll
        for (int r = 0; r < 4; r++) {
            int i = t + 256 * r, row = i >> 3, kq = i & 7;
            int b = row >> 4, e = row & 15;
            float4 v = *(const float4*)&g_S[(size_t)((b * 8 + h) * 16 + e) * 4096 + nb + k0 + kq * 4];
            float mm = m_s[row], ii = i_s[row];
            As[row][kq * 4 + 0] = wmma::__float_to_tf32(__expf(v.x - mm) * ii);
            As[row][kq * 4 + 1] = wmma::__float_to_tf32(__expf(v.y - mm) * ii);
            As[row][kq * 4 + 2] = wmma::__float_to_tf32(__expf(v.z - mm) * ii);
            As[row][kq * 4 + 3] = wmma::__float_to_tf32(__expf(v.w - mm) * ii);
        }
        #pragma unroll
        for (int r = 0; r < 2; r++) {
            int i = t + 256 * r, kk = i >> 4, dq = i & 15;
            float4 v = *(const float4*)&g_PE[(size_t)(nb + k0 + kk) * 512 + h * 64 + dq * 4];
            Bs[kk][dq * 4 + 0] = wmma::__float_to_tf32(v.x + bias_s[dq * 4 + 0]);
            Bs[kk][dq * 4 + 1] = wmma::__float_to_tf32(v.y + bias_s[dq * 4 + 1]);
            Bs[kk][dq * 4 + 2] = wmma::__float_to_tf32(v.z + bias_s[dq * 4 + 2]);
            Bs[kk][dq * 4 + 3] = wmma::__float_to_tf32(v.w + bias_s[dq * 4 + 3]);
        }
        __syncthreads();
        #pragma unroll
        for (int kf = 0; kf < 4; kf++) {
            wmma::fragment<wmma::matrix_a, 16, 16, 8, wmma::precision::tf32, wmma::row_major> af[2];
            wmma::fragment<wmma::matrix_b, 16, 16, 8, wmma::precision::tf32, wmma::row_major> bf[2];
            #pragma unroll
            for (int mi = 0; mi < 2; mi++)
                wmma::load_matrix_sync(af[mi], &As[wm * 32 + mi * 16][kf * 8], 36);
            #pragma unroll
            for (int ni = 0; ni < 2; ni++)
                wmma::load_matrix_sync(bf[ni], &Bs[kf * 8][wn * 32 + ni * 16], 68);
            #pragma unroll
            for (int mi = 0; mi < 2; mi++)
                #pragma unroll
                for (int ni = 0; ni < 2; ni++)
                    wmma::mma_sync(c[mi][ni], af[mi], bf[ni], c[mi][ni]);
        }
        __syncthreads();
    }
    #pragma unroll
    for (int mi = 0; mi < 2; mi++)
        #pragma unroll
        for (int ni = 0; ni < 2; ni++)
            wmma::store_matrix_sync(
                &g_OPEP[(size_t)((ks * 8 + h) * 128 + wm * 32 + mi * 16) * 64 + wn * 32 + ni * 16],
                c[mi][ni], 64, wmma::mem_row_major);
}

// ---------------- K9: out0 = (pa*wp-reduced) @ Wv + ope ---------------------------
__global__ void __launch_bounds__(512) k_out(const float* __restrict__ wkv,
                                             const float* __restrict__ wp) {
    __shared__ float pool[8192];
    __shared__ float ope_s[4][512];
    int row0 = blockIdx.x * 4;
    int t = threadIdx.x;
    for (int idx = t; idx < 8192; idx += 512) {
        int r = idx >> 11, rest = idx & 2047, h = rest >> 8, c = rest & 255;
        int row = row0 + r, b = row >> 4, e = row & 15;
        float s = 0.f;
        #pragma unroll
        for (int ks = 0; ks < 16; ks++)
            s += g_PAP[(size_t)((ks * 8 + b) * 128 + h * 16 + e) * 256 + c];
        pool[idx] = s * wp[c];
    }
    for (int idx = t; idx < 2048; idx += 512) {
        int r = idx >> 9, j = idx & 511;
        int row = row0 + r, b = row >> 4, e = row & 15;
        int h = j >> 6, d = j & 63;
        float s = 0.f;
        #pragma unroll
        for (int ks = 0; ks < 8; ks++)
            s += g_OPEP[(size_t)((ks * 8 + h) * 128 + b * 16 + e) * 64 + d];
        ope_s[r][j] = s;
    }
    __syncthreads();
    int tj = t & 127, tk = t >> 7;
    int h = tj >> 4;
    float4 acc[4];
    #pragma unroll
    for (int r = 0; r < 4; r++) acc[r] = make_float4(0.f, 0.f, 0.f, 0.f);
    #pragma unroll 4
    for (int c = tk * 64; c < tk * 64 + 64; c++) {
        float4 w4 = *(const float4*)&wkv[(size_t)c * 1024 + 512 + tj * 4];
        #pragma unroll
        for (int r = 0; r < 4; r++) {
            float p = pool[r * 2048 + h * 256 + c];
            acc[r].x += p * w4.x; acc[r].y += p * w4.y;
            acc[r].z += p * w4.z; acc[r].w += p * w4.w;
        }
    }
    __syncthreads();
    #pragma unroll
    for (int r = 0; r < 4; r++) *(float4*)&pool[(tk * 4 + r) * 512 + tj * 4] = acc[r];
    __syncthreads();
    {
        int r = t >> 7, j0 = (t & 127) * 4;
        float4 s = make_float4(0.f, 0.f, 0.f, 0.f);
        #pragma unroll
        for (int k2 = 0; k2 < 4; k2++) {
            float4 p = *(const float4*)&pool[(k2 * 4 + r) * 512 + j0];
            s.x += p.x; s.y += p.y; s.z += p.z; s.w += p.w;
        }
        float4 op = *(const float4*)&ope_s[r][j0];
        s.x += op.x; s.y += op.y; s.z += op.z; s.w += op.w;
        *(float4*)&g_ATT0[(row0 + r) * 512 + j0] = s;
    }
}

// ---------------- K10: proj + residual ---------------------------------------------
__global__ void __launch_bounds__(256) k_proj(const float* __restrict__ wproj,
                                              const float* __restrict__ bproj) {
    __shared__ float x_s[8][512];
    __shared__ float part[8][8][128];
    int row0 = blockIdx.x * 8, jb = blockIdx.y * 128, t = threadIdx.x;
    for (int idx = t; idx < 4096; idx += 256)
        x_s[idx >> 9][idx & 511] = g_ATT0[(row0 + (idx >> 9)) * 512 + (idx & 511)];
    __syncthreads();
    int tk = t >> 5, tj = t & 31, j = jb + tj * 4;
    float4 acc[8];
    #pragma unroll
    for (int r = 0; r < 8; r++) acc[r] = make_float4(0.f, 0.f, 0.f, 0.f);
    #pragma unroll 8
    for (int c = tk * 64; c < tk * 64 + 64; c++) {
        float4 w4 = *(const float4*)&wproj[(size_t)c * 512 + j];
        #pragma unroll
        for (int r = 0; r < 8; r++) {
            float x = x_s[r][c];
            acc[r].x += x * w4.x; acc[r].y += x * w4.y;
            acc[r].z += x * w4.z; acc[r].w += x * w4.w;
        }
    }
    #pragma unroll
    for (int r = 0; r < 8; r++) *(float4*)&part[tk][r][tj * 4] = acc[r];
    __syncthreads();
    {
        int r = t >> 5, cq = t & 31, j2 = jb + cq * 4;
        float4 s = make_float4(0.f, 0.f, 0.f, 0.f);
        #pragma unroll
        for (int k2 = 0; k2 < 8; k2++) {
            float4 p = *(const float4*)&part[k2][r][cq * 4];
            s.x += p.x; s.y += p.y; s.z += p.z; s.w += p.w;
        }
        float4 bp = *(const float4*)&bproj[j2];
        float4 mn = *(const float4*)&g_MOLN[(row0 + r) * 512 + j2];
        s.x += bp.x + mn.x; s.y += bp.y + mn.y;
        s.z += bp.z + mn.z; s.w += bp.w + mn.w;
        *(float4*)&g_ATT[(row0 + r) * 512 + j2] = s;
    }
}

// ---------------- K11: ffn1 (fused rmsnorm) + gelu ----------------------------------
__global__ void __launch_bounds__(256) k_ffn1(const float* __restrict__ nw,
                                              const float* __restrict__ w1,
                                              const float* __restrict__ b1) {
    __shared__ float x_s[8][512];
    __shared__ float part[8][8][128];
    int row0 = blockIdx.x * 8, jb = blockIdx.y * 128, t = threadIdx.x;
    int w = t >> 5, lane = t & 31;
    {
        float vals[16]; float ss = 0.f;
        #pragma unroll
        for (int i = 0; i < 16; i++) {
            float v = g_ATT[(row0 + w) * 512 + lane + i * 32];
            vals[i] = v; ss += v * v;
        }
        #pragma unroll
        for (int o = 16; o; o >>= 1) ss += __shfl_xor_sync(0xffffffffu, ss, o);
        float rv = rsqrtf(ss * (1.0f / 512.0f) + EPSV);
        #pragma unroll
        for (int i = 0; i < 16; i++) {
            int m = lane + i * 32;
            x_s[w][m] = vals[i] * rv * nw[m];
        }
    }
    __syncthreads();
    int tk = t >> 5, tj = t & 31, j = jb + tj * 4;
    float4 acc[8];
    #pragma unroll
    for (int r = 0; r < 8; r++) acc[r] = make_float4(0.f, 0.f, 0.f, 0.f);
    #pragma unroll 8
    for (int c = tk * 64; c < tk * 64 + 64; c++) {
        float4 w4 = *(const float4*)&w1[(size_t)c * 2048 + j];
        #pragma unroll
        for (int r = 0; r < 8; r++) {
            float x = x_s[r][c];
            acc[r].x += x * w4.x; acc[r].y += x * w4.y;
            acc[r].z += x * w4.z; acc[r].w += x * w4.w;
        }
    }
    #pragma unroll
    for (int r = 0; r < 8; r++) *(float4*)&part[tk][r][tj * 4] = acc[r];
    __syncthreads();
    {
        int r = t >> 5, cq = t & 31, j2 = jb + cq * 4;
        float4 s = make_float4(0.f, 0.f, 0.f, 0.f);
        #pragma unroll
        for (int k2 = 0; k2 < 8; k2++) {
            float4 p = *(const float4*)&part[k2][r][cq * 4];
            s.x += p.x; s.y += p.y; s.z += p.z; s.w += p.w;
        }
        float4 bb = *(const float4*)&b1[j2];
        float4 o;
        o.x = geluf(s.x + bb.x); o.y = geluf(s.y + bb.y);
        o.z = geluf(s.z + bb.z); o.w = geluf(s.w + bb.w);
        *(float4*)&g_H1[(size_t)(row0 + r) * 2048 + j2] = o;
    }
}

// ---------------- K12: ffn2 + residual ----------------------------------------------
__global__ void __launch_bounds__(512) k_ffn2(const float* __restrict__ w2,
                                              const float* __restrict__ b2,
                                              float* __restrict__ out) {
    __shared__ float pool[8192];
    int row0 = blockIdx.x * 4, jb = blockIdx.y * 128, t = threadIdx.x;
    for (int idx = t; idx < 8192; idx += 512)
        pool[idx] = g_H1[(size_t)(row0 + (idx >> 11)) * 2048 + (idx & 2047)];
    __syncthreads();
    int tk = t >> 5, tj = t & 31, j = jb + tj * 4;
    float4 acc[4];
    #pragma unroll
    for (int r = 0; r < 4; r++) acc[r] = make_float4(0.f, 0.f, 0.f, 0.f);
    #pragma unroll 8
    for (int c = tk * 128; c < tk * 128 + 128; c++) {
        float4 w4 = *(const float4*)&w2[(size_t)c * 512 + j];
        #pragma unroll
        for (int r = 0; r < 4; r++) {
            float x = pool[r * 2048 + c];
            acc[r].x += x * w4.x; acc[r].y += x * w4.y;
            acc[r].z += x * w4.z; acc[r].w += x * w4.w;
        }
    }
    __syncthreads();
    #pragma unroll
    for (int r = 0; r < 4; r++) *(float4*)&pool[tk * 512 + r * 128 + tj * 4] = acc[r];
    __syncthreads();
    {
        int r = t >> 7, cq = t & 127;
        float s = 0.f;
        #pragma unroll
        for (int k2 = 0; k2 < 16; k2++) s += pool[k2 * 512 + r * 128 + cq];
        int j2 = jb + cq;
        out[(row0 + r) * 512 + j2] = s + b2[j2] + g_ATT[(row0 + r) * 512 + j2];
    }
}

// ---------------- launch -------------------------------------------------------------
extern "C" void kernel_launch(void* const* d_in, const int* in_sizes, int n_in,
                              void* d_out, int out_size) {
    const float* patch   = (const float*)d_in[0];
    const float* mol     = (const float*)d_in[1];
    const float* pe_w1   = (const float*)d_in[2];
    const float* pe_b1   = (const float*)d_in[3];
    const float* pe_w2   = (const float*)d_in[4];
    const float* pe_b2   = (const float*)d_in[5];
    const float* wq      = (const float*)d_in[6];
    const float* bq      = (const float*)d_in[7];
    const float* wkv     = (const float*)d_in[8];
    const float* bkv     = (const float*)d_in[9];
    const float* wproj   = (const float*)d_in[10];
    const float* bproj   = (const float*)d_in[11];
    const float* nmolw   = (const float*)d_in[12];
    const float* npatchw = (const float*)d_in[13];
    const float* ffn_w1  = (const float*)d_in[14];
    const float* ffn_b1  = (const float*)d_in[15];
    const float* ffn_w2  = (const float*)d_in[16];
    const float* ffn_b2  = (const float*)d_in[17];
    const float* ffn_nw  = (const float*)d_in[18];
    float* out = (float*)d_out;
    (void)in_sizes; (void)n_in; (void)out_size;

    k_peg_tc   <<<dim3(32, 4), 256>>>(pe_w1, pe_b1, pe_w2);
    k_molq     <<<dim3(16, 4), 256>>>(mol, nmolw, wq, bq);
    k_tq2      <<<dim3(8, 2), 256>>>(wkv, npatchw);
    k_qpe_tc   <<<dim3(32, 8), 256>>>();
    k_scores_tc<<<dim3(32, 8), 256>>>(patch);
    k_msum     <<<1024, 512>>>();
    k_pa_tc    <<<dim3(16, 8), 512>>>(patch);
    k_ppe_tc   <<<dim3(8, 8), 256>>>(bkv, pe_b2);
    k_out      <<<32, 512>>>(wkv, npatchw);
    k_proj     <<<dim3(16, 4), 256>>>(wproj, bproj);
    k_ffn1     <<<dim3(16, 16), 256>>>(ffn_nw, ffn_w1, ffn_b1);
    k_ffn2     <<<dim3(32, 4), 512>>>(ffn_w2, ffn_b2, out);
}

// round 17
// speedup vs baseline: 1.0670x; 1.0405x over previous
#include <cuda_runtime.h>
#include <mma.h>
#include <math.h>

using namespace nvcuda;

#define BB 8
#define CC 256
#define NN 4096
#define MM 512
#define EE 16
#define NH 8
#define FFNH 2048
#define EPSV 1.1920929e-07f

// ------------- scratch (__device__ globals; no allocation allowed) ---------------
__device__ float g_PE  [NN * MM];             // pos_enc G@W2 (NO bias)
__device__ float g_RINV[BB * NN];             // patch rmsnorm rsqrt (written by k_scores_tc)
__device__ float g_Q   [128 * 512];           // q rows=(b,e) (includes bq)
__device__ float g_MOLN[128 * 512];           // normalized mol (residual)
__device__ float g_TQ  [BB * 128 * 256];      // tq' rows=(b, h*16+e), wp & 0.125 folded
__device__ float g_S   [(size_t)BB * 128 * NN];       // raw scores (never normalized in place)
__device__ float g_SMX [1024 * 2];            // per-row (max, 1/sum) for softmax
__device__ float g_PAP [(size_t)16 * BB * 128 * 256]; // pa partials   16.8 MB
__device__ float g_OPEP[16 * 8 * 128 * 64];   // p@(pe+bv+b2) partials (16 ksplit)
__device__ float g_ATT [128 * 512];           // attended (post residual)
__device__ float g_H1  [128 * 2048];          // ffn hidden

__device__ __forceinline__ float geluf(float x) {
    return 0.5f * x * (1.0f + erff(x * 0.70710678118654752440f));
}

template <int NWARPS, bool DOMAX>
__device__ __forceinline__ float blk_red(float v, float* red) {
    #pragma unroll
    for (int o = 16; o; o >>= 1) {
        float t = __shfl_xor_sync(0xffffffffu, v, o);
        v = DOMAX ? fmaxf(v, t) : v + t;
    }
    if ((threadIdx.x & 31) == 0) red[threadIdx.x >> 5] = v;
    __syncthreads();
    if (threadIdx.x < 32) {
        float r = (threadIdx.x < NWARPS) ? red[threadIdx.x] : (DOMAX ? -1e30f : 0.0f);
        #pragma unroll
        for (int o = NWARPS >> 1; o; o >>= 1) {
            float t = __shfl_xor_sync(0xffffffffu, r, o);
            r = DOMAX ? fmaxf(r, t) : r + t;
        }
        if (threadIdx.x == 0) red[0] = r;
    }
    __syncthreads();
    float s = red[0];
    __syncthreads();
    return s;
}

// ---------------- K1: PE = gelu(coords@W1+b1) @ W2 (tf32 TC, gelu fused) -----------
__global__ void __launch_bounds__(256) k_peg_tc(const float* __restrict__ w1,
                                                const float* __restrict__ b1,
                                                const float* __restrict__ w2) {
    __shared__ __align__(16) float As[128][36];
    __shared__ __align__(16) float Bs[32][132];
    int m0 = blockIdx.x * 128, j0 = blockIdx.y * 128, t = threadIdx.x;
    int w = t >> 5, wm = w >> 2, wn = w & 3;
    wmma::fragment<wmma::accumulator, 16, 16, 8, float> c[4][2];
    #pragma unroll
    for (int mi = 0; mi < 4; mi++)
        #pragma unroll
        for (int ni = 0; ni < 2; ni++) wmma::fill_fragment(c[mi][ni], 0.0f);
    for (int c0 = 0; c0 < 256; c0 += 32) {
        #pragma unroll
        for (int r = 0; r < 4; r++) {
            int i = t + 256 * r, row = i >> 3, kq = i & 7;
            int n = m0 + row;
            float cd = (float)(n >> 8)        * 0.0625f;
            float chc = (float)((n >> 4) & 15) * 0.0625f;
            float cw = (float)(n & 15)        * 0.0625f;
            int k = c0 + kq * 4;
            float4 wd = *(const float4*)&w1[k];
            float4 wh = *(const float4*)&w1[256 + k];
            float4 ww = *(const float4*)&w1[512 + k];
            float4 bb = *(const float4*)&b1[k];
            As[row][kq * 4 + 0] = wmma::__float_to_tf32(geluf(cd * wd.x + chc * wh.x + cw * ww.x + bb.x));
            As[row][kq * 4 + 1] = wmma::__float_to_tf32(geluf(cd * wd.y + chc * wh.y + cw * ww.y + bb.y));
            As[row][kq * 4 + 2] = wmma::__float_to_tf32(geluf(cd * wd.z + chc * wh.z + cw * ww.z + bb.z));
            As[row][kq * 4 + 3] = wmma::__float_to_tf32(geluf(cd * wd.w + chc * wh.w + cw * ww.w + bb.w));
        }
        #pragma unroll
        for (int r = 0; r < 4; r++) {
            int i = t + 256 * r, kk = i >> 5, nq = i & 31;
            float4 v = *(const float4*)&w2[(size_t)(c0 + kk) * 512 + j0 + nq * 4];
            Bs[kk][nq * 4 + 0] = wmma::__float_to_tf32(v.x);
            Bs[kk][nq * 4 + 1] = wmma::__float_to_tf32(v.y);
            Bs[kk][nq * 4 + 2] = wmma::__float_to_tf32(v.z);
            Bs[kk][nq * 4 + 3] = wmma::__float_to_tf32(v.w);
        }
        __syncthreads();
        #pragma unroll
        for (int kf = 0; kf < 4; kf++) {
            wmma::fragment<wmma::matrix_a, 16, 16, 8, wmma::precision::tf32, wmma::row_major> af[4];
            wmma::fragment<wmma::matrix_b, 16, 16, 8, wmma::precision::tf32, wmma::row_major> bf[2];
            #pragma unroll
            for (int mi = 0; mi < 4; mi++)
                wmma::load_matrix_sync(af[mi], &As[wm * 64 + mi * 16][kf * 8], 36);
            #pragma unroll
            for (int ni = 0; ni < 2; ni++)
                wmma::load_matrix_sync(bf[ni], &Bs[kf * 8][wn * 32 + ni * 16], 132);
            #pragma unroll
            for (int mi = 0; mi < 4; mi++)
                #pragma unroll
                for (int ni = 0; ni < 2; ni++)
                    wmma::mma_sync(c[mi][ni], af[mi], bf[ni], c[mi][ni]);
        }
        __syncthreads();
    }
    #pragma unroll
    for (int mi = 0; mi < 4; mi++)
        #pragma unroll
        for (int ni = 0; ni < 2; ni++)
            wmma::store_matrix_sync(&g_PE[(size_t)(m0 + wm * 64 + mi * 16) * 512 + j0 + wn * 32 + ni * 16],
                                    c[mi][ni], 512, wmma::mem_row_major);
}

// ---------------- K2: mol rmsnorm + Q projection (+bq) -----------------------------
__global__ void __launch_bounds__(256) k_molq(const float* __restrict__ mol,
                                              const float* __restrict__ wmol,
                                              const float* __restrict__ wq,
                                              const float* __restrict__ bq) {
    __shared__ float x_s[8][512];
    __shared__ float part[8][8][128];
    int row0 = blockIdx.x * 8, jb = blockIdx.y * 128;
    int t = threadIdx.x;
    int w = t >> 5, lane = t & 31;
    float vals[16]; float ss = 0.0f;
    #pragma unroll
    for (int i = 0; i < 16; i++) {
        float v = mol[(row0 + w) * 512 + lane + i * 32];
        vals[i] = v; ss += v * v;
    }
    #pragma unroll
    for (int o = 16; o; o >>= 1) ss += __shfl_xor_sync(0xffffffffu, ss, o);
    float rv = rsqrtf(ss * (1.0f / 512.0f) + EPSV);
    #pragma unroll
    for (int i = 0; i < 16; i++) {
        int m = lane + i * 32;
        float xn = vals[i] * rv * wmol[m];
        x_s[w][m] = xn;
        if (blockIdx.y == 0) g_MOLN[(row0 + w) * 512 + m] = xn;
    }
    __syncthreads();
    int tk = w, tj = lane, j = jb + tj * 4;
    float4 acc[8];
    #pragma unroll
    for (int r = 0; r < 8; r++) acc[r] = make_float4(0.f, 0.f, 0.f, 0.f);
    #pragma unroll 8
    for (int c = tk * 64; c < tk * 64 + 64; c++) {
        float4 w4 = *(const float4*)&wq[(size_t)c * 512 + j];
        #pragma unroll
        for (int r = 0; r < 8; r++) {
            float x = x_s[r][c];
            acc[r].x += x * w4.x; acc[r].y += x * w4.y;
            acc[r].z += x * w4.z; acc[r].w += x * w4.w;
        }
    }
    #pragma unroll
    for (int r = 0; r < 8; r++) *(float4*)&part[tk][r][tj * 4] = acc[r];
    __syncthreads();
    {
        int r = t >> 5, cq = t & 31, j2 = jb + cq * 4;
        float4 s = make_float4(0.f, 0.f, 0.f, 0.f);
        #pragma unroll
        for (int k2 = 0; k2 < 8; k2++) {
            float4 p = *(const float4*)&part[k2][r][cq * 4];
            s.x += p.x; s.y += p.y; s.z += p.z; s.w += p.w;
        }
        float4 bv = *(const float4*)&bq[j2];
        s.x += bv.x; s.y += bv.y; s.z += bv.z; s.w += bv.w;
        *(float4*)&g_Q[(row0 + r) * 512 + j2] = s;
    }
}

// ---------------- K3: tq' = 0.125*wp[c]*(q_h . Wk_h[c,:]) --------------------------
__global__ void __launch_bounds__(256) k_tq2(const float* __restrict__ wkv,
                                             const float* __restrict__ wp) {
    __shared__ float As[16][128];
    __shared__ float Bs[16][128];
    int h = blockIdx.x, c0b = blockIdx.y * 128, t = threadIdx.x;
    int tr = t >> 4, tc = t & 15;
    float acc[8][8];
    #pragma unroll
    for (int i = 0; i < 8; i++)
        #pragma unroll
        for (int j = 0; j < 8; j++) acc[i][j] = 0.f;
    for (int k0 = 0; k0 < 64; k0 += 16) {
        {
            int r = t >> 1, k8 = (t & 1) * 8;
            const float* src = &g_Q[r * 512 + h * 64 + k0 + k8];
            float4 a0 = *(const float4*)&src[0];
            float4 a1 = *(const float4*)&src[4];
            As[k8 + 0][r] = a0.x; As[k8 + 1][r] = a0.y; As[k8 + 2][r] = a0.z; As[k8 + 3][r] = a0.w;
            As[k8 + 4][r] = a1.x; As[k8 + 5][r] = a1.y; As[k8 + 6][r] = a1.z; As[k8 + 7][r] = a1.w;
        }
        {
            int c = t >> 1, k8 = (t & 1) * 8;
            const float* src = &wkv[(size_t)(c0b + c) * 1024 + h * 64 + k0 + k8];
            float4 v0 = *(const float4*)&src[0];
            float4 v1 = *(const float4*)&src[4];
            Bs[k8 + 0][c] = v0.x; Bs[k8 + 1][c] = v0.y; Bs[k8 + 2][c] = v0.z; Bs[k8 + 3][c] = v0.w;
            Bs[k8 + 4][c] = v1.x; Bs[k8 + 5][c] = v1.y; Bs[k8 + 6][c] = v1.z; Bs[k8 + 7][c] = v1.w;
        }
        __syncthreads();
        #pragma unroll
        for (int kk = 0; kk < 16; kk++) {
            float4 a0 = *(const float4*)&As[kk][tr * 8];
            float4 a1 = *(const float4*)&As[kk][tr * 8 + 4];
            float4 b0 = *(const float4*)&Bs[kk][tc * 8];
            float4 b1 = *(const float4*)&Bs[kk][tc * 8 + 4];
            float a[8] = {a0.x, a0.y, a0.z, a0.w, a1.x, a1.y, a1.z, a1.w};
            float bb[8] = {b0.x, b0.y, b0.z, b0.w, b1.x, b1.y, b1.z, b1.w};
            #pragma unroll
            for (int i = 0; i < 8; i++)
                #pragma unroll
                for (int j = 0; j < 8; j++) acc[i][j] += a[i] * bb[j];
        }
        __syncthreads();
    }
    float4 wp0 = *(const float4*)&wp[c0b + tc * 8];
    float4 wp1 = *(const float4*)&wp[c0b + tc * 8 + 4];
    float wpv[8] = {wp0.x, wp0.y, wp0.z, wp0.w, wp1.x, wp1.y, wp1.z, wp1.w};
    #pragma unroll
    for (int i = 0; i < 8; i++) {
        int r = tr * 8 + i, b = r >> 4, e = r & 15;
        float* dst = &g_TQ[(size_t)(b * 128 + h * 16 + e) * 256 + c0b + tc * 8];
        #pragma unroll
        for (int j = 0; j < 8; j++) dst[j] = acc[i][j] * wpv[j] * 0.125f;
    }
}

// ---------------- K4: S = (0.125*q_h) @ PE_h^T  (tf32 TC, K=64, col-major B) -------
__global__ void __launch_bounds__(256) k_qpe_tc() {
    __shared__ __align__(16) float As[128][36];
    __shared__ __align__(16) float Bs[128][36];
    int n0 = blockIdx.x * 128, h = blockIdx.y, t = threadIdx.x;
    int w = t >> 5, wm = w >> 2, wn = w & 3;
    wmma::fragment<wmma::accumulator, 16, 16, 8, float> c[4][2];
    #pragma unroll
    for (int mi = 0; mi < 4; mi++)
        #pragma unroll
        for (int ni = 0; ni < 2; ni++) wmma::fill_fragment(c[mi][ni], 0.0f);
    for (int c0 = 0; c0 < 64; c0 += 32) {
        #pragma unroll
        for (int r = 0; r < 4; r++) {
            int i = t + 256 * r, row = i >> 3, kq = i & 7;
            float4 v = *(const float4*)&g_Q[row * 512 + h * 64 + c0 + kq * 4];
            As[row][kq * 4 + 0] = wmma::__float_to_tf32(0.125f * v.x);
            As[row][kq * 4 + 1] = wmma::__float_to_tf32(0.125f * v.y);
            As[row][kq * 4 + 2] = wmma::__float_to_tf32(0.125f * v.z);
            As[row][kq * 4 + 3] = wmma::__float_to_tf32(0.125f * v.w);
        }
        #pragma unroll
        for (int r = 0; r < 4; r++) {
            int i = t + 256 * r, row = i >> 3, kq = i & 7;
            float4 v = *(const float4*)&g_PE[(size_t)(n0 + row) * 512 + h * 64 + c0 + kq * 4];
            Bs[row][kq * 4 + 0] = wmma::__float_to_tf32(v.x);
            Bs[row][kq * 4 + 1] = wmma::__float_to_tf32(v.y);
            Bs[row][kq * 4 + 2] = wmma::__float_to_tf32(v.z);
            Bs[row][kq * 4 + 3] = wmma::__float_to_tf32(v.w);
        }
        __syncthreads();
        #pragma unroll
        for (int kf = 0; kf < 4; kf++) {
            wmma::fragment<wmma::matrix_a, 16, 16, 8, wmma::precision::tf32, wmma::row_major> af[4];
            wmma::fragment<wmma::matrix_b, 16, 16, 8, wmma::precision::tf32, wmma::col_major> bf[2];
            #pragma unroll
            for (int mi = 0; mi < 4; mi++)
                wmma::load_matrix_sync(af[mi], &As[wm * 64 + mi * 16][kf * 8], 36);
            #pragma unroll
            for (int ni = 0; ni < 2; ni++)
                wmma::load_matrix_sync(bf[ni], &Bs[wn * 32 + ni * 16][kf * 8], 36);
            #pragma unroll
            for (int mi = 0; mi < 4; mi++)
                #pragma unroll
                for (int ni = 0; ni < 2; ni++)
                    wmma::mma_sync(c[mi][ni], af[mi], bf[ni], c[mi][ni]);
        }
        __syncthreads();
    }
    #pragma unroll
    for (int mi = 0; mi < 4; mi++) {
        int r0 = wm * 64 + mi * 16;
        int b = r0 >> 4;
        float* dst = &g_S[(size_t)((b * 8 + h) * 16) * 4096 + n0 + wn * 32];
        #pragma unroll
        for (int ni = 0; ni < 2; ni++)
            wmma::store_matrix_sync(dst + ni * 16, c[mi][ni], 4096, wmma::mem_row_major);
    }
}

// ---------------- K5: scores (tf32 TC, rinv fused): S += tq' @ (X*rinv) ------------
__global__ void __launch_bounds__(256) k_scores_tc(const float* __restrict__ X) {
    __shared__ __align__(16) float As[128][36];
    __shared__ __align__(16) float Bs[32][132];
    __shared__ __align__(16) float rs[128];
    __shared__ float ss2[256];
    int n0 = blockIdx.x * 128, b = blockIdx.y, t = threadIdx.x;
    int w = t >> 5, wm = w >> 2, wn = w & 3;
    const float* Xb = X + (size_t)b * CC * NN;
    const float* TQ = g_TQ + (size_t)b * 128 * 256;
    float* Sb = g_S + (size_t)b * 128 * 4096;
    {
        int tn = t & 127, chh = t >> 7;
        const float* xp = Xb + (size_t)(chh * 128) * 4096 + n0 + tn;
        float s0 = 0.f, s1 = 0.f, s2 = 0.f, s3 = 0.f;
        #pragma unroll 4
        for (int c = 0; c < 128; c += 4) {
            float v0 = xp[(size_t)(c + 0) * 4096];
            float v1 = xp[(size_t)(c + 1) * 4096];
            float v2 = xp[(size_t)(c + 2) * 4096];
            float v3 = xp[(size_t)(c + 3) * 4096];
            s0 += v0 * v0; s1 += v1 * v1; s2 += v2 * v2; s3 += v3 * v3;
        }
        ss2[t] = (s0 + s1) + (s2 + s3);
    }
    __syncthreads();
    if (t < 128) {
        float rv = rsqrtf((ss2[t] + ss2[t + 128]) * (1.0f / 256.0f) + EPSV);
        rs[t] = rv;
        g_RINV[b * 4096 + n0 + t] = rv;
    }
    __syncthreads();
    wmma::fragment<wmma::accumulator, 16, 16, 8, float> c[4][2];
    #pragma unroll
    for (int mi = 0; mi < 4; mi++)
        #pragma unroll
        for (int ni = 0; ni < 2; ni++)
            wmma::load_matrix_sync(c[mi][ni],
                &Sb[(size_t)(wm * 64 + mi * 16) * 4096 + n0 + wn * 32 + ni * 16],
                4096, wmma::mem_row_major);
    for (int c0 = 0; c0 < 256; c0 += 32) {
        #pragma unroll
        for (int r = 0; r < 4; r++) {
            int i = t + 256 * r, row = i >> 3, kq = i & 7;
            float4 v = *(const float4*)&TQ[(size_t)row * 256 + c0 + kq * 4];
            As[row][kq * 4 + 0] = wmma::__float_to_tf32(v.x);
            As[row][kq * 4 + 1] = wmma::__float_to_tf32(v.y);
            As[row][kq * 4 + 2] = wmma::__float_to_tf32(v.z);
            As[row][kq * 4 + 3] = wmma::__float_to_tf32(v.w);
        }
        #pragma unroll
        for (int r = 0; r < 4; r++) {
            int i = t + 256 * r, kk = i >> 5, nq = i & 31;
            float4 v = *(const float4*)&Xb[(size_t)(c0 + kk) * 4096 + n0 + nq * 4];
            Bs[kk][nq * 4 + 0] = wmma::__float_to_tf32(v.x * rs[nq * 4 + 0]);
            Bs[kk][nq * 4 + 1] = wmma::__float_to_tf32(v.y * rs[nq * 4 + 1]);
            Bs[kk][nq * 4 + 2] = wmma::__float_to_tf32(v.z * rs[nq * 4 + 2]);
            Bs[kk][nq * 4 + 3] = wmma::__float_to_tf32(v.w * rs[nq * 4 + 3]);
        }
        __syncthreads();
        #pragma unroll
        for (int kf = 0; kf < 4; kf++) {
            wmma::fragment<wmma::matrix_a, 16, 16, 8, wmma::precision::tf32, wmma::row_major> af[4];
            wmma::fragment<wmma::matrix_b, 16, 16, 8, wmma::precision::tf32, wmma::row_major> bf[2];
            #pragma unroll
            for (int mi = 0; mi < 4; mi++)
                wmma::load_matrix_sync(af[mi], &As[wm * 64 + mi * 16][kf * 8], 36);
            #pragma unroll
            for (int ni = 0; ni < 2; ni++)
                wmma::load_matrix_sync(bf[ni], &Bs[kf * 8][wn * 32 + ni * 16], 132);
            #pragma unroll
            for (int mi = 0; mi < 4; mi++)
                #pragma unroll
                for (int ni = 0; ni < 2; ni++)
                    wmma::mma_sync(c[mi][ni], af[mi], bf[ni], c[mi][ni]);
        }
        __syncthreads();
    }
    #pragma unroll
    for (int mi = 0; mi < 4; mi++)
        #pragma unroll
        for (int ni = 0; ni < 2; ni++)
            wmma::store_matrix_sync(&Sb[(size_t)(wm * 64 + mi * 16) * 4096 + n0 + wn * 32 + ni * 16],
                                    c[mi][ni], 4096, wmma::mem_row_major);
}

// ---------------- K6: msum — per-row softmax (max, 1/sum); S left raw --------------
__global__ void k_msum() {
    __shared__ float red[32];
    int row = blockIdx.x;   // 0..1023
    const float* s = g_S + (size_t)row * NN;
    int t = threadIdx.x;    // 512
    float loc[8];
    float m = -1e30f;
    #pragma unroll
    for (int i = 0; i < 8; i++) { loc[i] = s[t + i * 512]; m = fmaxf(m, loc[i]); }
    m = blk_red<16, true>(m, red);
    float sum = 0.0f;
    #pragma unroll
    for (int i = 0; i < 8; i++) sum += __expf(loc[i] - m);
    sum = blk_red<16, false>(sum, red);
    if (t == 0) {
        g_SMX[row * 2 + 0] = m;
        g_SMX[row * 2 + 1] = 1.0f / sum;
    }
}

// ---------------- K7: pa partials (tf32 TC): softmax applied in staging ------------
__global__ void __launch_bounds__(512) k_pa_tc(const float* __restrict__ X) {
    __shared__ __align__(16) float As[128][20];
    __shared__ __align__(16) float Bs[256][20];
    int ks = blockIdx.x, b = blockIdx.y, t = threadIdx.x;
    int nbase = ks * 256;
    int w = t >> 5, wm = w >> 3, wn = w & 7;
    const float* Xb = X + (size_t)b * CC * NN;
    int arow = t >> 2;
    float smx_m   = g_SMX[(b * 128 + arow) * 2 + 0];
    float smx_inv = g_SMX[(b * 128 + arow) * 2 + 1];
    wmma::fragment<wmma::accumulator, 16, 16, 8, float> c[4][2];
    #pragma unroll
    for (int mi = 0; mi < 4; mi++)
        #pragma unroll
        for (int ni = 0; ni < 2; ni++) wmma::fill_fragment(c[mi][ni], 0.0f);
    for (int k0 = 0; k0 < 256; k0 += 16) {
        {
            int kq = t & 3;
            int n = nbase + k0 + kq * 4;
            float4 p  = *(const float4*)&g_S[(size_t)(b * 128 + arow) * 4096 + n];
            float4 rv = *(const float4*)&g_RINV[b * 4096 + n];
            As[arow][kq * 4 + 0] = wmma::__float_to_tf32(__expf(p.x - smx_m) * smx_inv * rv.x);
            As[arow][kq * 4 + 1] = wmma::__float_to_tf32(__expf(p.y - smx_m) * smx_inv * rv.y);
            As[arow][kq * 4 + 2] = wmma::__float_to_tf32(__expf(p.z - smx_m) * smx_inv * rv.z);
            As[arow][kq * 4 + 3] = wmma::__float_to_tf32(__expf(p.w - smx_m) * smx_inv * rv.w);
        }
        #pragma unroll
        for (int r = 0; r < 2; r++) {
            int i = t + 512 * r, cc = i >> 2, kq = i & 3;
            float4 v = *(const float4*)&Xb[(size_t)cc * 4096 + nbase + k0 + kq * 4];
            Bs[cc][kq * 4 + 0] = wmma::__float_to_tf32(v.x);
            Bs[cc][kq * 4 + 1] = wmma::__float_to_tf32(v.y);
            Bs[cc][kq * 4 + 2] = wmma::__float_to_tf32(v.z);
            Bs[cc][kq * 4 + 3] = wmma::__float_to_tf32(v.w);
        }
        __syncthreads();
        #pragma unroll
        for (int kf = 0; kf < 2; kf++) {
            wmma::fragment<wmma::matrix_a, 16, 16, 8, wmma::precision::tf32, wmma::row_major> af[4];
            wmma::fragment<wmma::matrix_b, 16, 16, 8, wmma::precision::tf32, wmma::col_major> bf[2];
            #pragma unroll
            for (int mi = 0; mi < 4; mi++)
                wmma::load_matrix_sync(af[mi], &As[wm * 64 + mi * 16][kf * 8], 20);
            #pragma unroll
            for (int ni = 0; ni < 2; ni++)
                wmma::load_matrix_sync(bf[ni], &Bs[wn * 32 + ni * 16][kf * 8], 20);
            #pragma unroll
            for (int mi = 0; mi < 4; mi++)
                #pragma unroll
                for (int ni = 0; ni < 2; ni++)
                    wmma::mma_sync(c[mi][ni], af[mi], bf[ni], c[mi][ni]);
        }
        __syncthreads();
    }
    #pragma unroll
    for (int mi = 0; mi < 4; mi++)
        #pragma unroll
        for (int ni = 0; ni < 2; ni++)
            wmma::store_matrix_sync(
                &g_PAP[(size_t)((ks * 8 + b) * 128 + wm * 64 + mi * 16) * 256 + wn * 32 + ni * 16],
                c[mi][ni], 256, wmma::mem_row_major);
}

// ---------------- K8: ope partials (tf32 TC): 16 ksplit, Kchunk=256 ----------------
__global__ void __launch_bounds__(256) k_ppe_tc(const float* __restrict__ bkv,
                                                const float* __restrict__ peb2) {
    __shared__ __align__(16) float As[128][36];
    __shared__ __align__(16) float Bs[32][68];
    __shared__ float bias_s[64];
    __shared__ float m_s[128];
    __shared__ float i_s[128];
    int h = blockIdx.x, ks = blockIdx.y, t = threadIdx.x;
    int nb = ks * 256;
    int w = t >> 5, wm = w >> 1, wn = w & 1;
    if (t < 16) {
        float4 bv4 = *(const float4*)&bkv[512 + h * 64 + t * 4];
        float4 b24 = *(const float4*)&peb2[h * 64 + t * 4];
        bias_s[t * 4 + 0] = bv4.x + b24.x;
        bias_s[t * 4 + 1] = bv4.y + b24.y;
        bias_s[t * 4 + 2] = bv4.z + b24.z;
        bias_s[t * 4 + 3] = bv4.w + b24.w;
    }
    if (t < 128) {
        int b = t >> 4, e = t & 15;
        int sr = (b * 8 + h) * 16 + e;
        m_s[t] = g_SMX[sr * 2 + 0];
        i_s[t] = g_SMX[sr * 2 + 1];
    }
    __syncthreads();
    wmma::fragment<wmma::accumulator, 16, 16, 8, float> c[2][2];
    #pragma unroll
    for (int mi = 0; mi < 2; mi++)
        #pragma unroll
        for (int ni = 0; ni < 2; ni++) wmma::fill_fragment(c[mi][ni], 0.0f);
    for (int k0 = 0; k0 < 256; k0 += 32) {
        #pragma unroll
        for (int r = 0; r < 4; r++) {
            int i = t + 256 * r, row = i >> 3, kq = i & 7;
            int b = row >> 4, e = row & 15;
            float4 v = *(const float4*)&g_S[(size_t)((b * 8 + h) * 16 + e) * 4096 + nb + k0 + kq * 4];
            float mm = m_s[row], ii = i_s[row];
            As[row][kq * 4 + 0] = wmma::__float_to_tf32(__expf(v.x - mm) * ii);
            As[row][kq * 4 + 1] = wmma::__float_to_tf32(__expf(v.y - mm) * ii);
            As[row][kq * 4 + 2] = wmma::__float_to_tf32(__expf(v.z - mm) * ii);
            As[row][kq * 4 + 3] = wmma::__float_to_tf32(__expf(v.w - mm) * ii);
        }
        #pragma unroll
        for (int r = 0; r < 2; r++) {
            int i = t + 256 * r, kk = i >> 4, dq = i & 15;
            float4 v = *(const float4*)&g_PE[(size_t)(nb + k0 + kk) * 512 + h * 64 + dq * 4];
            Bs[kk][dq * 4 + 0] = wmma::__float_to_tf32(v.x + bias_s[dq * 4 + 0]);
            Bs[kk][dq * 4 + 1] = wmma::__float_to_tf32(v.y + bias_s[dq * 4 + 1]);
            Bs[kk][dq * 4 + 2] = wmma::__float_to_tf32(v.z + bias_s[dq * 4 + 2]);
            Bs[kk][dq * 4 + 3] = wmma::__float_to_tf32(v.w + bias_s[dq * 4 + 3]);
        }
        __syncthreads();
        #pragma unroll
        for (int kf = 0; kf < 4; kf++) {
            wmma::fragment<wmma::matrix_a, 16, 16, 8, wmma::precision::tf32, wmma::row_major> af[2];
            wmma::fragment<wmma::matrix_b, 16, 16, 8, wmma::precision::tf32, wmma::row_major> bf[2];
            #pragma unroll
            for (int mi = 0; mi < 2; mi++)
                wmma::load_matrix_sync(af[mi], &As[wm * 32 + mi * 16][kf * 8], 36);
            #pragma unroll
            for (int ni = 0; ni < 2; ni++)
                wmma::load_matrix_sync(bf[ni], &Bs[kf * 8][wn * 32 + ni * 16], 68);
            #pragma unroll
            for (int mi = 0; mi < 2; mi++)
                #pragma unroll
                for (int ni = 0; ni < 2; ni++)
                    wmma::mma_sync(c[mi][ni], af[mi], bf[ni], c[mi][ni]);
        }
        __syncthreads();
    }
    #pragma unroll
    for (int mi = 0; mi < 2; mi++)
        #pragma unroll
        for (int ni = 0; ni < 2; ni++)
            wmma::store_matrix_sync(
                &g_OPEP[(size_t)((ks * 8 + h) * 128 + wm * 32 + mi * 16) * 64 + wn * 32 + ni * 16],
                c[mi][ni], 64, wmma::mem_row_major);
}

// ---------------- K9: fused out+proj: attn-out rows -> proj -> +residual -----------
// grid(32), 512 thr. Phase 1 = old k_out into smem; phase 2 = proj GEMM + residual.
__global__ void __launch_bounds__(512) k_outproj(const float* __restrict__ wkv,
                                                 const float* __restrict__ wp,
                                                 const float* __restrict__ wproj,
                                                 const float* __restrict__ bproj) {
    __shared__ float pool[8192];       // 32 KB, reused across phases
    __shared__ float ope_s[4][512];    // ope partials, then attn-out rows (in place)
    int row0 = blockIdx.x * 4;
    int t = threadIdx.x;
    for (int idx = t; idx < 8192; idx += 512) {
        int r = idx >> 11, rest = idx & 2047, h = rest >> 8, c = rest & 255;
        int row = row0 + r, b = row >> 4, e = row & 15;
        float s = 0.f;
        #pragma unroll
        for (int ks = 0; ks < 16; ks++)
            s += g_PAP[(size_t)((ks * 8 + b) * 128 + h * 16 + e) * 256 + c];
        pool[idx] = s * wp[c];
    }
    for (int idx = t; idx < 2048; idx += 512) {
        int r = idx >> 9, j = idx & 511;
        int row = row0 + r, b = row >> 4, e = row & 15;
        int h = j >> 6, d = j & 63;
        float s = 0.f;
        #pragma unroll
        for (int ks = 0; ks < 16; ks++)
            s += g_OPEP[(size_t)((ks * 8 + h) * 128 + b * 16 + e) * 64 + d];
        ope_s[r][j] = s;
    }
    __syncthreads();
    // V GEMM: (pa*wp) @ Wv  (per-h K=256)
    {
        int tj = t & 127, tk = t >> 7;
        int h = tj >> 4;
        float4 acc[4];
        #pragma unroll
        for (int r = 0; r < 4; r++) acc[r] = make_float4(0.f, 0.f, 0.f, 0.f);
        #pragma unroll 4
        for (int c = tk * 64; c < tk * 64 + 64; c++) {
            float4 w4 = *(const float4*)&wkv[(size_t)c * 1024 + 512 + tj * 4];
            #pragma unroll
            for (int r = 0; r < 4; r++) {
                float p = pool[r * 2048 + h * 256 + c];
                acc[r].x += p * w4.x; acc[r].y += p * w4.y;
                acc[r].z += p * w4.z; acc[r].w += p * w4.w;
            }
        }
        __syncthreads();
        #pragma unroll
        for (int r = 0; r < 4; r++) *(float4*)&pool[(tk * 4 + r) * 512 + tj * 4] = acc[r];
    }
    __syncthreads();
    // reduce 4 ksplits + ope -> attn-out rows, stored in-place in ope_s
    {
        int r = t >> 7, j0 = (t & 127) * 4;
        float4 s = make_float4(0.f, 0.f, 0.f, 0.f);
        #pragma unroll
        for (int k2 = 0; k2 < 4; k2++) {
            float4 p = *(const float4*)&pool[(k2 * 4 + r) * 512 + j0];
            s.x += p.x; s.y += p.y; s.z += p.z; s.w += p.w;
        }
        float4 op = *(const float4*)&ope_s[r][j0];
        s.x += op.x; s.y += op.y; s.z += op.z; s.w += op.w;
        *(float4*)&ope_s[r][j0] = s;   // in-place: thread owns exactly these 4
    }
    __syncthreads();
    // proj GEMM: out = att0 @ wproj + bproj + MOLN, K=512 split 4 ways
    {
        int tj = t & 127, tk = t >> 7;
        int j = tj * 4;
        float4 acc[4];
        #pragma unroll
        for (int r = 0; r < 4; r++) acc[r] = make_float4(0.f, 0.f, 0.f, 0.f);
        #pragma unroll 8
        for (int c = tk * 128; c < tk * 128 + 128; c++) {
            float4 w4 = *(const float4*)&wproj[(size_t)c * 512 + j];
            #pragma unroll
            for (int r = 0; r < 4; r++) {
                float x = ope_s[r][c];
                acc[r].x += x * w4.x; acc[r].y += x * w4.y;
                acc[r].z += x * w4.z; acc[r].w += x * w4.w;
            }
        }
        __syncthreads();
        #pragma unroll
        for (int r = 0; r < 4; r++) *(float4*)&pool[(tk * 4 + r) * 512 + tj * 4] = acc[r];
    }
    __syncthreads();
    {
        int r = t >> 7, j0 = (t & 127) * 4;
        float4 s = make_float4(0.f, 0.f, 0.f, 0.f);
        #pragma unroll
        for (int k2 = 0; k2 < 4; k2++) {
            float4 p = *(const float4*)&pool[(k2 * 4 + r) * 512 + j0];
            s.x += p.x; s.y += p.y; s.z += p.z; s.w += p.w;
        }
        float4 bp = *(const float4*)&bproj[j0];
        float4 mn = *(const float4*)&g_MOLN[(row0 + r) * 512 + j0];
        s.x += bp.x + mn.x; s.y += bp.y + mn.y;
        s.z += bp.z + mn.z; s.w += bp.w + mn.w;
        *(float4*)&g_ATT[(row0 + r) * 512 + j0] = s;
    }
}

// ---------------- K10: ffn1 (fused rmsnorm) + gelu ----------------------------------
__global__ void __launch_bounds__(256) k_ffn1(const float* __restrict__ nw,
                                              const float* __restrict__ w1,
                                              const float* __restrict__ b1) {
    __shared__ float x_s[8][512];
    __shared__ float part[8][8][128];
    int row0 = blockIdx.x * 8, jb = blockIdx.y * 128, t = threadIdx.x;
    int w = t >> 5, lane = t & 31;
    {
        float vals[16]; float ss = 0.f;
        #pragma unroll
        for (int i = 0; i < 16; i++) {
            float v = g_ATT[(row0 + w) * 512 + lane + i * 32];
            vals[i] = v; ss += v * v;
        }
        #pragma unroll
        for (int o = 16; o; o >>= 1) ss += __shfl_xor_sync(0xffffffffu, ss, o);
        float rv = rsqrtf(ss * (1.0f / 512.0f) + EPSV);
        #pragma unroll
        for (int i = 0; i < 16; i++) {
            int m = lane + i * 32;
            x_s[w][m] = vals[i] * rv * nw[m];
        }
    }
    __syncthreads();
    int tk = t >> 5, tj = t & 31, j = jb + tj * 4;
    float4 acc[8];
    #pragma unroll
    for (int r = 0; r < 8; r++) acc[r] = make_float4(0.f, 0.f, 0.f, 0.f);
    #pragma unroll 8
    for (int c = tk * 64; c < tk * 64 + 64; c++) {
        float4 w4 = *(const float4*)&w1[(size_t)c * 2048 + j];
        #pragma unroll
        for (int r = 0; r < 8; r++) {
            float x = x_s[r][c];
            acc[r].x += x * w4.x; acc[r].y += x * w4.y;
            acc[r].z += x * w4.z; acc[r].w += x * w4.w;
        }
    }
    #pragma unroll
    for (int r = 0; r < 8; r++) *(float4*)&part[tk][r][tj * 4] = acc[r];
    __syncthreads();
    {
        int r = t >> 5, cq = t & 31, j2 = jb + cq * 4;
        float4 s = make_float4(0.f, 0.f, 0.f, 0.f);
        #pragma unroll
        for (int k2 = 0; k2 < 8; k2++) {
            float4 p = *(const float4*)&part[k2][r][cq * 4];
            s.x += p.x; s.y += p.y; s.z += p.z; s.w += p.w;
        }
        float4 bb = *(const float4*)&b1[j2];
        float4 o;
        o.x = geluf(s.x + bb.x); o.y = geluf(s.y + bb.y);
        o.z = geluf(s.z + bb.z); o.w = geluf(s.w + bb.w);
        *(float4*)&g_H1[(size_t)(row0 + r) * 2048 + j2] = o;
    }
}

// ---------------- K11: ffn2 + residual ----------------------------------------------
__global__ void __launch_bounds__(512) k_ffn2(const float* __restrict__ w2,
                                              const float* __restrict__ b2,
                                              float* __restrict__ out) {
    __shared__ float pool[8192];
    int row0 = blockIdx.x * 4, jb = blockIdx.y * 128, t = threadIdx.x;
    for (int idx = t; idx < 8192; idx += 512)
        pool[idx] = g_H1[(size_t)(row0 + (idx >> 11)) * 2048 + (idx & 2047)];
    __syncthreads();
    int tk = t >> 5, tj = t & 31, j = jb + tj * 4;
    float4 acc[4];
    #pragma unroll
    for (int r = 0; r < 4; r++) acc[r] = make_float4(0.f, 0.f, 0.f, 0.f);
    #pragma unroll 8
    for (int c = tk * 128; c < tk * 128 + 128; c++) {
        float4 w4 = *(const float4*)&w2[(size_t)c * 512 + j];
        #pragma unroll
        for (int r = 0; r < 4; r++) {
            float x = pool[r * 2048 + c];
            acc[r].x += x * w4.x; acc[r].y += x * w4.y;
            acc[r].z += x * w4.z; acc[r].w += x * w4.w;
        }
    }
    __syncthreads();
    #pragma unroll
    for (int r = 0; r < 4; r++) *(float4*)&pool[tk * 512 + r * 128 + tj * 4] = acc[r];
    __syncthreads();
    {
        int r = t >> 7, cq = t & 127;
        float s = 0.f;
        #pragma unroll
        for (int k2 = 0; k2 < 16; k2++) s += pool[k2 * 512 + r * 128 + cq];
        int j2 = jb + cq;
        out[(row0 + r) * 512 + j2] = s + b2[j2] + g_ATT[(row0 + r) * 512 + j2];
    }
}

// ---------------- launch -------------------------------------------------------------
extern "C" void kernel_launch(void* const* d_in, const int* in_sizes, int n_in,
                              void* d_out, int out_size) {
    const float* patch   = (const float*)d_in[0];
    const float* mol     = (const float*)d_in[1];
    const float* pe_w1   = (const float*)d_in[2];
    const float* pe_b1   = (const float*)d_in[3];
    const float* pe_w2   = (const float*)d_in[4];
    const float* pe_b2   = (const float*)d_in[5];
    const float* wq      = (const float*)d_in[6];
    const float* bq      = (const float*)d_in[7];
    const float* wkv     = (const float*)d_in[8];
    const float* bkv     = (const float*)d_in[9];
    const float* wproj   = (const float*)d_in[10];
    const float* bproj   = (const float*)d_in[11];
    const float* nmolw   = (const float*)d_in[12];
    const float* npatchw = (const float*)d_in[13];
    const float* ffn_w1  = (const float*)d_in[14];
    const float* ffn_b1  = (const float*)d_in[15];
    const float* ffn_w2  = (const float*)d_in[16];
    const float* ffn_b2  = (const float*)d_in[17];
    const float* ffn_nw  = (const float*)d_in[18];
    float* out = (float*)d_out;
    (void)in_sizes; (void)n_in; (void)out_size;

    k_peg_tc   <<<dim3(32, 4), 256>>>(pe_w1, pe_b1, pe_w2);
    k_molq     <<<dim3(16, 4), 256>>>(mol, nmolw, wq, bq);
    k_tq2      <<<dim3(8, 2), 256>>>(wkv, npatchw);
    k_qpe_tc   <<<dim3(32, 8), 256>>>();
    k_scores_tc<<<dim3(32, 8), 256>>>(patch);
    k_msum     <<<1024, 512>>>();
    k_pa_tc    <<<dim3(16, 8), 512>>>(patch);
    k_ppe_tc   <<<dim3(8, 16), 256>>>(bkv, pe_b2);
    k_outproj  <<<32, 512>>>(wkv, npatchw, wproj, bproj);
    k_ffn1     <<<dim3(16, 16), 256>>>(ffn_nw, ffn_w1, ffn_b1);
    k_ffn2     <<<dim3(32, 4), 512>>>(ffn_w2, ffn_b2, out);
}